// round 1
// baseline (speedup 1.0000x reference)
#include <cuda_runtime.h>
#include <cuda_bf16.h>
#include <math.h>

#define BB 16
#define DKK 512
#define NN 1024
#define MMM 1024

// ---------------- scratch (device globals; no runtime allocation) ----------------
__device__ float g_scores[(size_t)BB * NN * MMM];   // 64 MB
__device__ float g_sc[BB * NN];                     // slack column (per row)
__device__ float g_sr[BB * MMM];                    // slack row (per col)
__device__ float g_col_lse[BB * MMM];               // deferred column LSE
__device__ float g_weights[BB * NN];                // row sums of perm
__device__ float g_wt[BB * 3 * NN];                 // weighted_tgt [B,3,N]

// ---------------- init ----------------
__global__ void init_kernel() {
    int i = blockIdx.x * blockDim.x + threadIdx.x;
    if (i < BB * NN)  g_sc[i] = 0.0f;
    if (i < BB * MMM) g_sr[i] = 0.0f;
}

// ---------------- GEMM: scores[b,n,m] = sum_d A[b,d,n]*B[b,d,m] * alpha_b ----------------
__global__ __launch_bounds__(256) void gemm_kernel(const float* __restrict__ A,
                                                   const float* __restrict__ Bm,
                                                   const float* __restrict__ temp) {
    __shared__ float As[16][128];
    __shared__ float Bs[16][128];
    const int bmt = blockIdx.x;   // m tile
    const int bnt = blockIdx.y;   // n tile
    const int bb  = blockIdx.z;
    const float* Ab = A  + (size_t)bb * DKK * NN  + bnt * 128;
    const float* Bb = Bm + (size_t)bb * DKK * MMM + bmt * 128;
    const int t  = threadIdx.x;
    const int lr = t >> 5;          // 0..7
    const int lc = (t & 31) << 2;   // 0..124
    const int tn = (t >> 4) << 3;   // 0..120
    const int tm = (t & 15) << 3;

    float acc[8][8];
#pragma unroll
    for (int i = 0; i < 8; i++)
#pragma unroll
        for (int j = 0; j < 8; j++) acc[i][j] = 0.0f;

    for (int k0 = 0; k0 < DKK; k0 += 16) {
#pragma unroll
        for (int i = 0; i < 2; i++) {
            int r = lr + 8 * i;
            *(float4*)(&As[r][lc]) = *(const float4*)(Ab + (size_t)(k0 + r) * NN  + lc);
            *(float4*)(&Bs[r][lc]) = *(const float4*)(Bb + (size_t)(k0 + r) * MMM + lc);
        }
        __syncthreads();
#pragma unroll
        for (int k = 0; k < 16; k++) {
            float a[8], b[8];
            *(float4*)(a)     = *(float4*)(&As[k][tn]);
            *(float4*)(a + 4) = *(float4*)(&As[k][tn + 4]);
            *(float4*)(b)     = *(float4*)(&Bs[k][tm]);
            *(float4*)(b + 4) = *(float4*)(&Bs[k][tm + 4]);
#pragma unroll
            for (int i = 0; i < 8; i++)
#pragma unroll
                for (int j = 0; j < 8; j++) acc[i][j] += a[i] * b[j];
        }
        __syncthreads();
    }

    const float alpha = rsqrtf((float)DKK) / temp[bb];
    float* C = g_scores + (size_t)bb * NN * MMM + (size_t)(bnt * 128 + tn) * MMM + bmt * 128 + tm;
#pragma unroll
    for (int i = 0; i < 8; i++) {
        float4 v0, v1;
        v0.x = acc[i][0] * alpha; v0.y = acc[i][1] * alpha;
        v0.z = acc[i][2] * alpha; v0.w = acc[i][3] * alpha;
        v1.x = acc[i][4] * alpha; v1.y = acc[i][5] * alpha;
        v1.z = acc[i][6] * alpha; v1.w = acc[i][7] * alpha;
        *(float4*)(C + (size_t)i * MMM)     = v0;
        *(float4*)(C + (size_t)i * MMM + 4) = v1;
    }
}

// ---------------- row normalize (optionally applying deferred col LSE first) ----------------
__global__ __launch_bounds__(256) void row_pass_kernel(int apply_col) {
    const int gw   = (blockIdx.x * 256 + threadIdx.x) >> 5;  // global row id (b*N+n)
    const int lane = threadIdx.x & 31;
    const int bb   = gw >> 10;
    float* row = g_scores + (size_t)gw * MMM;
    const float* clse = g_col_lse + bb * MMM;

    float x[32];
    float mx = -1e30f;
#pragma unroll
    for (int i = 0; i < 8; i++) {
        int off = i * 128 + lane * 4;
        float4 v = *(float4*)(row + off);
        if (apply_col) {
            float4 c = *(const float4*)(clse + off);
            v.x -= c.x; v.y -= c.y; v.z -= c.z; v.w -= c.w;
        }
        x[4 * i] = v.x; x[4 * i + 1] = v.y; x[4 * i + 2] = v.z; x[4 * i + 3] = v.w;
        mx = fmaxf(mx, fmaxf(fmaxf(v.x, v.y), fmaxf(v.z, v.w)));
    }
    float sc = g_sc[gw];
#pragma unroll
    for (int o = 16; o > 0; o >>= 1) mx = fmaxf(mx, __shfl_xor_sync(0xffffffffu, mx, o));
    mx = fmaxf(mx, sc);

    float s = 0.0f;
#pragma unroll
    for (int i = 0; i < 32; i++) s += expf(x[i] - mx);
#pragma unroll
    for (int o = 16; o > 0; o >>= 1) s += __shfl_xor_sync(0xffffffffu, s, o);
    s += expf(sc - mx);

    const float lse = mx + logf(s);
#pragma unroll
    for (int i = 0; i < 8; i++) {
        int off = i * 128 + lane * 4;
        float4 v;
        v.x = x[4 * i] - lse; v.y = x[4 * i + 1] - lse;
        v.z = x[4 * i + 2] - lse; v.w = x[4 * i + 3] - lse;
        *(float4*)(row + off) = v;
    }
    if (lane == 0) g_sc[gw] = sc - lse;
}

// ---------------- column LSE stats (no matrix write; subtraction deferred) ----------------
__global__ __launch_bounds__(256) void col_pass_kernel() {
    const int bb = blockIdx.y;
    const int c  = threadIdx.x & 63;
    const int g  = threadIdx.x >> 6;            // 0..3 row groups
    const int m  = blockIdx.x * 64 + c;
    const float* base = g_scores + (size_t)bb * NN * MMM + m;

    float mx = -1e30f, s = 0.0f;
    for (int n = g; n < NN; n += 4) {
        float x = base[(size_t)n * MMM];
        if (x > mx) { s = s * expf(mx - x) + 1.0f; mx = x; }
        else        { s += expf(x - mx); }
    }
    __shared__ float smx[256], ssm[256];
    smx[threadIdx.x] = mx; ssm[threadIdx.x] = s;
    __syncthreads();
    if (g == 0) {
#pragma unroll
        for (int j = 1; j < 4; j++) {
            float m2 = smx[c + 64 * j], s2 = ssm[c + 64 * j];
            if (m2 > mx) { s = s * expf(mx - m2) + s2; mx = m2; }
            else         { s += s2 * expf(m2 - mx); }
        }
        float sr = g_sr[bb * MMM + m];
        if (sr > mx) { s = s * expf(mx - sr) + 1.0f; mx = sr; }
        else         { s += expf(sr - mx); }
        float lse = mx + logf(s);
        g_col_lse[bb * MMM + m] = lse;
        g_sr[bb * MMM + m] = sr - lse;
    }
}

// ---------------- exp + row-normalize + weighted_tgt; writes perm_norm ----------------
__global__ __launch_bounds__(256) void final_pass_kernel(const float* __restrict__ tgt,
                                                         float* __restrict__ out_pn) {
    const int gw   = (blockIdx.x * 256 + threadIdx.x) >> 5;
    const int lane = threadIdx.x & 31;
    const int bb   = gw >> 10;
    const int n    = gw & 1023;
    const float* row  = g_scores + (size_t)gw * MMM;
    const float* clse = g_col_lse + bb * MMM;

    float p[32];
    float sum = 0.0f;
#pragma unroll
    for (int i = 0; i < 8; i++) {
        int off = i * 128 + lane * 4;
        float4 v = *(const float4*)(row + off);
        float4 c = *(const float4*)(clse + off);
        float p0 = expf(v.x - c.x), p1 = expf(v.y - c.y);
        float p2 = expf(v.z - c.z), p3 = expf(v.w - c.w);
        p[4 * i] = p0; p[4 * i + 1] = p1; p[4 * i + 2] = p2; p[4 * i + 3] = p3;
        sum += p0 + p1 + p2 + p3;
    }
#pragma unroll
    for (int o = 16; o > 0; o >>= 1) sum += __shfl_xor_sync(0xffffffffu, sum, o);

    const float inv = 1.0f / (sum + 1e-8f);
    const float* t0 = tgt + (size_t)bb * 3 * MMM;
    float w0 = 0.0f, w1 = 0.0f, w2 = 0.0f;
    float* outrow = out_pn + (size_t)gw * MMM;
#pragma unroll
    for (int i = 0; i < 8; i++) {
        int off = i * 128 + lane * 4;
        float4 q;
        q.x = p[4 * i] * inv; q.y = p[4 * i + 1] * inv;
        q.z = p[4 * i + 2] * inv; q.w = p[4 * i + 3] * inv;
        *(float4*)(outrow + off) = q;
        float4 ta = *(const float4*)(t0 + off);
        float4 tb = *(const float4*)(t0 + MMM + off);
        float4 tc = *(const float4*)(t0 + 2 * MMM + off);
        w0 += q.x * ta.x + q.y * ta.y + q.z * ta.z + q.w * ta.w;
        w1 += q.x * tb.x + q.y * tb.y + q.z * tb.z + q.w * tb.w;
        w2 += q.x * tc.x + q.y * tc.y + q.z * tc.z + q.w * tc.w;
    }
#pragma unroll
    for (int o = 16; o > 0; o >>= 1) {
        w0 += __shfl_xor_sync(0xffffffffu, w0, o);
        w1 += __shfl_xor_sync(0xffffffffu, w1, o);
        w2 += __shfl_xor_sync(0xffffffffu, w2, o);
    }
    if (lane == 0) {
        g_weights[gw] = sum;
        g_wt[(size_t)bb * 3 * NN + n]           = w0;
        g_wt[(size_t)bb * 3 * NN + NN + n]      = w1;
        g_wt[(size_t)bb * 3 * NN + 2 * NN + n]  = w2;
    }
}

// ---------------- per-batch Procrustes (double precision 3x3 SVD) ----------------
__device__ double block_reduce_d(double v, double* sred, int tid) {
    sred[tid] = v; __syncthreads();
    for (int s = 128; s > 0; s >>= 1) {
        if (tid < s) sred[tid] += sred[tid + s];
        __syncthreads();
    }
    double r = sred[0]; __syncthreads();
    return r;
}

__global__ __launch_bounds__(256) void procrustes_kernel(const float* __restrict__ src,
                                                         float* __restrict__ out) {
    const int bb = blockIdx.x, tid = threadIdx.x;
    __shared__ double sred[256];
    __shared__ double bc[16];

    const float* w  = g_weights + bb * NN;
    const float* wt = g_wt + (size_t)bb * 3 * NN;
    const float* sp = src  + (size_t)bb * 3 * NN;

    double lv = 0.0;
    for (int n = tid; n < NN; n += 256) lv += (double)w[n];
    double wsum = block_reduce_d(lv, sred, tid);
    double denom = wsum + 1e-8;

    double acc[6] = {0, 0, 0, 0, 0, 0};
    for (int n = tid; n < NN; n += 256) {
        double wn = (double)w[n] / denom;
        acc[0] += (double)sp[n] * wn;
        acc[1] += (double)sp[NN + n] * wn;
        acc[2] += (double)sp[2 * NN + n] * wn;
        acc[3] += (double)wt[n] * wn;
        acc[4] += (double)wt[NN + n] * wn;
        acc[5] += (double)wt[2 * NN + n] * wn;
    }
    for (int q = 0; q < 6; q++) {
        double r = block_reduce_d(acc[q], sred, tid);
        if (tid == 0) bc[q] = r;
    }
    __syncthreads();
    double scent[3] = {bc[0], bc[1], bc[2]};
    double tcent[3] = {bc[3], bc[4], bc[5]};

    double h[9] = {0, 0, 0, 0, 0, 0, 0, 0, 0};
    for (int n = tid; n < NN; n += 256) {
        double wn = (double)w[n] / denom;
        double si[3] = {(double)sp[n] - scent[0],
                        (double)sp[NN + n] - scent[1],
                        (double)sp[2 * NN + n] - scent[2]};
        double tj[3] = {((double)wt[n] - tcent[0]) * wn,
                        ((double)wt[NN + n] - tcent[1]) * wn,
                        ((double)wt[2 * NN + n] - tcent[2]) * wn};
#pragma unroll
        for (int i = 0; i < 3; i++)
#pragma unroll
            for (int j = 0; j < 3; j++) h[i * 3 + j] += si[i] * tj[j];
    }
    for (int q = 0; q < 9; q++) {
        double r = block_reduce_d(h[q], sred, tid);
        if (tid == 0) bc[q] = r;
    }
    __syncthreads();

    if (tid == 0) {
        double H[3][3];
        for (int i = 0; i < 3; i++)
            for (int j = 0; j < 3; j++) H[i][j] = bc[i * 3 + j];

        // A = H^T H (symmetric PSD), Jacobi eigendecomposition
        double A[3][3];
        for (int i = 0; i < 3; i++)
            for (int j = 0; j < 3; j++)
                A[i][j] = H[0][i] * H[0][j] + H[1][i] * H[1][j] + H[2][i] * H[2][j];
        double V[3][3] = {{1, 0, 0}, {0, 1, 0}, {0, 0, 1}};
        for (int sweep = 0; sweep < 45; sweep++) {
            int r3 = sweep % 3;
            int p = (r3 == 2) ? 1 : 0;
            int q = (r3 == 0) ? 1 : 2;
            double apq = A[p][q];
            if (fabs(apq) < 1e-280) continue;
            double theta = (A[q][q] - A[p][p]) / (2.0 * apq);
            double tt = copysign(1.0, theta) / (fabs(theta) + sqrt(theta * theta + 1.0));
            double cc = 1.0 / sqrt(tt * tt + 1.0);
            double ssn = tt * cc;
            for (int k = 0; k < 3; k++) {
                double akp = A[k][p], akq = A[k][q];
                A[k][p] = cc * akp - ssn * akq;
                A[k][q] = ssn * akp + cc * akq;
            }
            for (int k = 0; k < 3; k++) {
                double apk = A[p][k], aqk = A[q][k];
                A[p][k] = cc * apk - ssn * aqk;
                A[q][k] = ssn * apk + cc * aqk;
            }
            for (int k = 0; k < 3; k++) {
                double vkp = V[k][p], vkq = V[k][q];
                V[k][p] = cc * vkp - ssn * vkq;
                V[k][q] = ssn * vkp + cc * vkq;
            }
        }
        double ev[3] = {A[0][0], A[1][1], A[2][2]};
        int idx[3] = {0, 1, 2};
        if (ev[idx[0]] < ev[idx[1]]) { int t2 = idx[0]; idx[0] = idx[1]; idx[1] = t2; }
        if (ev[idx[0]] < ev[idx[2]]) { int t2 = idx[0]; idx[0] = idx[2]; idx[2] = t2; }
        if (ev[idx[1]] < ev[idx[2]]) { int t2 = idx[1]; idx[1] = idx[2]; idx[2] = t2; }

        double Vs[3][3], U[3][3];
        for (int k = 0; k < 3; k++) {
            int c = idx[k];
            double sv = sqrt(fmax(ev[c], 0.0));
            double invs = (sv > 1e-30) ? 1.0 / sv : 0.0;
            for (int i = 0; i < 3; i++) Vs[i][k] = V[i][c];
            for (int i = 0; i < 3; i++)
                U[i][k] = (H[i][0] * V[0][c] + H[i][1] * V[1][c] + H[i][2] * V[2][c]) * invs;
        }
        double detH = H[0][0] * (H[1][1] * H[2][2] - H[1][2] * H[2][1])
                    - H[0][1] * (H[1][0] * H[2][2] - H[1][2] * H[2][0])
                    + H[0][2] * (H[1][0] * H[2][1] - H[1][1] * H[2][0]);
        double dsg = (detH >= 0.0) ? 1.0 : -1.0;
        double R[3][3];
        for (int i = 0; i < 3; i++)
            for (int j = 0; j < 3; j++)
                R[i][j] = Vs[i][0] * U[j][0] + Vs[i][1] * U[j][1] + dsg * Vs[i][2] * U[j][2];
        double tv[3];
        for (int i = 0; i < 3; i++)
            tv[i] = -(R[i][0] * scent[0] + R[i][1] * scent[1] + R[i][2] * scent[2]) + tcent[i];

        for (int i = 0; i < 3; i++)
            for (int j = 0; j < 3; j++)
                out[bb * 9 + i * 3 + j] = (float)R[i][j];
        for (int i = 0; i < 3; i++)
            out[BB * 9 + bb * 3 + i] = (float)tv[i];
    }
}

// ---------------- launch ----------------
extern "C" void kernel_launch(void* const* d_in, const int* in_sizes, int n_in,
                              void* d_out, int out_size) {
    const float* src_emb = (const float*)d_in[0];
    const float* tgt_emb = (const float*)d_in[1];
    const float* src     = (const float*)d_in[2];
    const float* tgt     = (const float*)d_in[3];
    const float* temp    = (const float*)d_in[4];
    float* out = (float*)d_out;
    float* out_pn = out + BB * 9 + BB * 3;   // perm_norm after R and t

    init_kernel<<<64, 256>>>();
    gemm_kernel<<<dim3(MMM / 128, NN / 128, BB), 256>>>(src_emb, tgt_emb, temp);
    for (int it = 0; it < 5; it++) {
        row_pass_kernel<<<(BB * NN) / 8, 256>>>(it > 0 ? 1 : 0);
        col_pass_kernel<<<dim3(MMM / 64, BB), 256>>>();
    }
    final_pass_kernel<<<(BB * NN) / 8, 256>>>(tgt, out_pn);
    procrustes_kernel<<<BB, 256>>>(src, out);
}

// round 3
// speedup vs baseline: 1.6555x; 1.6555x over previous
#include <cuda_runtime.h>
#include <cuda_bf16.h>
#include <math.h>
#include <stdint.h>

#define BB 16
#define DKK 512
#define NN 1024
#define MMM 1024

// ---------------- scratch (device globals) ----------------
__device__ float g_scores[(size_t)BB * NN * MMM];          // affinity, 64 MB (written once by GEMM)
__device__ __nv_bfloat16 g_shi[(size_t)BB * NN * DKK];     // src hi, transposed [b][n][d]
__device__ __nv_bfloat16 g_slo[(size_t)BB * NN * DKK];
__device__ __nv_bfloat16 g_thi[(size_t)BB * MMM * DKK];    // tgt hi, transposed [b][m][d]
__device__ __nv_bfloat16 g_tlo[(size_t)BB * MMM * DKK];
__device__ float g_cp[(size_t)BB * 128 * MMM];             // column partial sums, 8 MB
__device__ float g_r[BB * NN];                             // row duals (cumulative)
__device__ float g_c[BB * MMM];                            // col duals (cumulative)
__device__ float g_weights[BB * NN];
__device__ float g_wt[BB * 3 * NN];

// ---------------- PTX helpers (sm_80-class only; no arch-specific ops) ----------------
__device__ __forceinline__ uint32_t smem_u32(const void* p) {
    uint32_t a;
    asm("{ .reg .u64 t; cvta.to.shared.u64 t, %1; cvt.u32.u64 %0, t; }" : "=r"(a) : "l"(p));
    return a;
}
#define LDSM4(r0, r1, r2, r3, addr) \
    asm volatile("ldmatrix.sync.aligned.m8n8.x4.shared.b16 {%0,%1,%2,%3}, [%4];" \
        : "=r"(r0), "=r"(r1), "=r"(r2), "=r"(r3) : "r"(addr))
#define MMA16816(c, a, b0, b1) \
    asm volatile("mma.sync.aligned.m16n8k16.row.col.f32.bf16.bf16.f32 " \
        "{%0,%1,%2,%3}, {%4,%5,%6,%7}, {%8,%9}, {%0,%1,%2,%3};" \
        : "+f"((c)[0]), "+f"((c)[1]), "+f"((c)[2]), "+f"((c)[3]) \
        : "r"((a)[0]), "r"((a)[1]), "r"((a)[2]), "r"((a)[3]), "r"(b0), "r"(b1))
#define CPASYNC16(saddr, gptr) \
    asm volatile("cp.async.cg.shared.global [%0], [%1], 16;" :: "r"(saddr), "l"(gptr))
#define CP_COMMIT() asm volatile("cp.async.commit_group;" ::: "memory")
#define CP_WAIT1()  asm volatile("cp.async.wait_group 1;" ::: "memory")
#define CP_WAIT0()  asm volatile("cp.async.wait_group 0;" ::: "memory")

// ---------------- init: zero column duals ----------------
__global__ void init_kernel() {
    int i = blockIdx.x * blockDim.x + threadIdx.x;
    if (i < BB * MMM) g_c[i] = 0.0f;
}

// ---------------- transpose + hi/lo bf16 split ----------------
// in: [b][d][n] fp32 (n contiguous) -> out hi/lo: [b][n][d] bf16 (d contiguous)
__global__ __launch_bounds__(256) void convert_kernel(const float* __restrict__ srcE,
                                                      const float* __restrict__ tgtE) {
    __shared__ float s[32][33];
    const int z = blockIdx.z;
    const int bb = z & 15;
    const float* in = (z < 16) ? srcE : tgtE;
    __nv_bfloat16* hi = (z < 16) ? g_shi : g_thi;
    __nv_bfloat16* lo = (z < 16) ? g_slo : g_tlo;
    const int tx = threadIdx.x, ty = threadIdx.y;   // (32, 8)
    const int n = blockIdx.x * 32 + tx;
    const int d0 = blockIdx.y * 32;
#pragma unroll
    for (int j = 0; j < 4; j++)
        s[ty + 8 * j][tx] = in[((size_t)bb * DKK + d0 + ty + 8 * j) * NN + n];
    __syncthreads();
    const int dd = d0 + tx;
#pragma unroll
    for (int j = 0; j < 4; j++) {
        int nn = blockIdx.x * 32 + ty + 8 * j;
        float v = s[tx][ty + 8 * j];
        __nv_bfloat16 h = __float2bfloat16(v);
        float rem = v - __bfloat162float(h);
        size_t o = ((size_t)bb * NN + nn) * DKK + dd;
        hi[o] = h;
        lo[o] = __float2bfloat16(rem);
    }
}

// ---------------- bf16-split GEMM via mma.sync (sm_80 PTX, tensor pipe) ----------------
// C[b, n, m] = alpha_b * sum_d src[b,d,n]*tgt[b,d,m]
// CTA tile 128x128 (rows=n, cols=m); 8 warps each 64x32; K chunks of 32, double buffered.
// smem per stage: Ahi/Alo/Bhi/Blo each 128 rows x 80B (32 bf16 padded) = 40960 B.
#define STAGE_BYTES 40960
#define ROWB 80

__global__ __launch_bounds__(256, 1) void gemm_mma(const float* __restrict__ temp) {
    extern __shared__ char sm_[];
    const uint32_t sb = smem_u32(sm_);
    const int tid = threadIdx.x, wid = tid >> 5, lane = tid & 31;
    const int mt = blockIdx.x, nt = blockIdx.y, bb = blockIdx.z;
    const int warp_m = wid & 1;     // 2 warps over 128 rows (64 each)
    const int warp_n = wid >> 1;    // 4 warps over 128 cols (32 each)

    const __nv_bfloat16* Ah = g_shi + ((size_t)bb * NN + nt * 128) * DKK;
    const __nv_bfloat16* Al = g_slo + ((size_t)bb * NN + nt * 128) * DKK;
    const __nv_bfloat16* Bh = g_thi + ((size_t)bb * MMM + mt * 128) * DKK;
    const __nv_bfloat16* Bl = g_tlo + ((size_t)bb * MMM + mt * 128) * DKK;

    // stage loader: 2048 x 16B chunks, 8 per thread
    auto stage_load = [&](int kc, int s) {
#pragma unroll
        for (int i = 0; i < 8; i++) {
            int q = tid + i * 256;
            int mat = q >> 9;          // 0..3: Ahi,Alo,Bhi,Blo
            int w = q & 511;
            int row = w >> 2, c = w & 3;
            const __nv_bfloat16* base =
                (mat < 2) ? ((mat == 0) ? Ah : Al) : ((mat == 2) ? Bh : Bl);
            uint32_t saddr = sb + s * STAGE_BYTES + mat * 10240 + row * ROWB + c * 16;
            const char* g = (const char*)(base + (size_t)row * DKK + kc * 32 + c * 8);
            CPASYNC16(saddr, g);
        }
        CP_COMMIT();
    };

    float acc[4][4][4];
#pragma unroll
    for (int i = 0; i < 4; i++)
#pragma unroll
        for (int j = 0; j < 4; j++)
#pragma unroll
            for (int k = 0; k < 4; k++) acc[i][j][k] = 0.0f;

    stage_load(0, 0);

    for (int kc = 0; kc < 16; kc++) {
        const int s = kc & 1;
        if (kc + 1 < 16) { stage_load(kc + 1, s ^ 1); CP_WAIT1(); }
        else             { CP_WAIT0(); }
        __syncthreads();

        const uint32_t Abase = sb + s * STAGE_BYTES + (warp_m * 64) * ROWB;
        const uint32_t Bbase = sb + s * STAGE_BYTES + 20480 + (warp_n * 32) * ROWB;

#pragma unroll
        for (int h = 0; h < 2; h++) {       // two k16 steps per 32-chunk
            uint32_t ah[4][4], al[4][4], bh[2][4], bl[2][4];
#pragma unroll
            for (int m4 = 0; m4 < 4; m4++) {
                uint32_t ad = Abase + (uint32_t)((m4 * 16 + (lane & 15)) * ROWB
                             + (h * 2 + (lane >> 4)) * 16);
                LDSM4(ah[m4][0], ah[m4][1], ah[m4][2], ah[m4][3], ad);
                LDSM4(al[m4][0], al[m4][1], al[m4][2], al[m4][3], ad + 10240);
            }
#pragma unroll
            for (int np = 0; np < 2; np++) {
                uint32_t bd = Bbase + (uint32_t)((np * 16 + ((lane >> 4) & 1) * 8 + (lane & 7)) * ROWB
                             + (h * 2 + ((lane >> 3) & 1)) * 16);
                LDSM4(bh[np][0], bh[np][1], bh[np][2], bh[np][3], bd);
                LDSM4(bl[np][0], bl[np][1], bl[np][2], bl[np][3], bd + 10240);
            }
#pragma unroll
            for (int m4 = 0; m4 < 4; m4++)
#pragma unroll
                for (int n8 = 0; n8 < 4; n8++) {
                    const int np = n8 >> 1, hf = (n8 & 1) * 2;
                    MMA16816(acc[m4][n8], ah[m4], bh[np][hf], bh[np][hf + 1]);
                    MMA16816(acc[m4][n8], ah[m4], bl[np][hf], bl[np][hf + 1]);
                    MMA16816(acc[m4][n8], al[m4], bh[np][hf], bh[np][hf + 1]);
                }
        }
        __syncthreads();
    }

    // ---- epilogue: stage through smem (132-float padded rows), coalesced out ----
    float* smF = (float*)sm_;
#pragma unroll
    for (int m4 = 0; m4 < 4; m4++)
#pragma unroll
        for (int n8 = 0; n8 < 4; n8++) {
            int r0 = warp_m * 64 + m4 * 16 + (lane >> 2);
            int col = warp_n * 32 + n8 * 8 + (lane & 3) * 2;
            *(float2*)(smF + r0 * 132 + col)       = make_float2(acc[m4][n8][0], acc[m4][n8][1]);
            *(float2*)(smF + (r0 + 8) * 132 + col) = make_float2(acc[m4][n8][2], acc[m4][n8][3]);
        }
    __syncthreads();

    const float alpha = rsqrtf((float)DKK) / temp[bb];
    float* C = g_scores + (size_t)bb * NN * MMM + (size_t)(nt * 128) * MMM + mt * 128;
#pragma unroll
    for (int i = 0; i < 16; i++) {
        int idx = tid + i * 256;            // 0..4095
        int row = idx >> 5, c4 = idx & 31;
        float4 v = *(float4*)(smF + row * 132 + c4 * 4);
        v.x *= alpha; v.y *= alpha; v.z *= alpha; v.w *= alpha;
        *(float4*)(C + (size_t)row * MMM + c4 * 4) = v;
    }
}

// ---------------- row pass: r[n] = LSE_m(aff - c, 0); emit column exp-partials ----------------
__global__ __launch_bounds__(256) void row_kernel() {
    __shared__ float s_p[8][1024];
    __shared__ float s_scale[8];
    const int w    = threadIdx.x >> 5;
    const int lane = threadIdx.x & 31;
    const int gw   = blockIdx.x * 8 + w;
    const int bb   = gw >> 10;
    const float* aff = g_scores + (size_t)gw * MMM;
    const float* c   = g_c + bb * MMM;

    float x[32];
    float mx = 0.0f;    // slack term 0 included in max
#pragma unroll
    for (int i = 0; i < 8; i++) {
        int off = i * 128 + lane * 4;
        float4 a = *(const float4*)(aff + off);
        float4 cc = *(const float4*)(c + off);
        x[4 * i]     = a.x - cc.x;
        x[4 * i + 1] = a.y - cc.y;
        x[4 * i + 2] = a.z - cc.z;
        x[4 * i + 3] = a.w - cc.w;
        mx = fmaxf(mx, fmaxf(fmaxf(x[4 * i], x[4 * i + 1]), fmaxf(x[4 * i + 2], x[4 * i + 3])));
    }
#pragma unroll
    for (int o = 16; o > 0; o >>= 1) mx = fmaxf(mx, __shfl_xor_sync(0xffffffffu, mx, o));

    float s = 0.0f;
#pragma unroll
    for (int i = 0; i < 8; i++) {
        int off = i * 128 + lane * 4;
        float4 e;
        e.x = __expf(x[4 * i] - mx);     e.y = __expf(x[4 * i + 1] - mx);
        e.z = __expf(x[4 * i + 2] - mx); e.w = __expf(x[4 * i + 3] - mx);
        *(float4*)(&s_p[w][off]) = e;    // unscaled partials; per-warp scale applied at reduce
        s += e.x + e.y + e.z + e.w;
    }
#pragma unroll
    for (int o = 16; o > 0; o >>= 1) s += __shfl_xor_sync(0xffffffffu, s, o);
    s += __expf(-mx);                    // slack

    const float r = mx + logf(s);
    if (lane == 0) {
        g_r[gw] = r;
        s_scale[w] = __expf(mx - r);     // e^{mx-r} = 1/s
    }
    __syncthreads();

    const int t = threadIdx.x;
    float4 acc = make_float4(0.f, 0.f, 0.f, 0.f);
#pragma unroll
    for (int ww = 0; ww < 8; ww++) {
        float sc = s_scale[ww];
        float4 v = *(const float4*)(&s_p[ww][t * 4]);
        acc.x += v.x * sc; acc.y += v.y * sc; acc.z += v.z * sc; acc.w += v.w * sc;
    }
    const int rb = blockIdx.x & 127;
    *(float4*)(g_cp + ((size_t)(bb * 128 + rb)) * 1024 + t * 4) = acc;
}

// ---------------- column reduce: c = c_old + log(S + exp(-c_old)) ----------------
__global__ __launch_bounds__(256) void colreduce_kernel() {
    const int idx = blockIdx.x * 256 + threadIdx.x;   // < 16384
    const int b = idx >> 10, m = idx & 1023;
    const float* cp = g_cp + (size_t)b * 128 * 1024 + m;
    float S = 0.0f;
#pragma unroll 8
    for (int rb = 0; rb < 128; rb++) S += cp[(size_t)rb * 1024];
    const float co = g_c[idx];
    g_c[idx] = co + logf(S + __expf(-co));
}

// ---------------- final: perm_norm, weights, weighted_tgt ----------------
__global__ __launch_bounds__(256) void final_kernel(const float* __restrict__ tgt,
                                                    float* __restrict__ out_pn) {
    const int gw   = (blockIdx.x * 256 + threadIdx.x) >> 5;
    const int lane = threadIdx.x & 31;
    const int bb   = gw >> 10;
    const int n    = gw & 1023;
    const float* aff = g_scores + (size_t)gw * MMM;
    const float* c   = g_c + bb * MMM;
    const float r    = g_r[gw];

    float p[32];
    float sum = 0.0f;
#pragma unroll
    for (int i = 0; i < 8; i++) {
        int off = i * 128 + lane * 4;
        float4 a = *(const float4*)(aff + off);
        float4 cc = *(const float4*)(c + off);
        float p0 = __expf(a.x - cc.x - r), p1 = __expf(a.y - cc.y - r);
        float p2 = __expf(a.z - cc.z - r), p3 = __expf(a.w - cc.w - r);
        p[4 * i] = p0; p[4 * i + 1] = p1; p[4 * i + 2] = p2; p[4 * i + 3] = p3;
        sum += p0 + p1 + p2 + p3;
    }
#pragma unroll
    for (int o = 16; o > 0; o >>= 1) sum += __shfl_xor_sync(0xffffffffu, sum, o);

    const float inv = 1.0f / (sum + 1e-8f);
    const float* t0 = tgt + (size_t)bb * 3 * MMM;
    float w0 = 0.0f, w1 = 0.0f, w2 = 0.0f;
    float* outrow = out_pn + (size_t)gw * MMM;
#pragma unroll
    for (int i = 0; i < 8; i++) {
        int off = i * 128 + lane * 4;
        float4 q;
        q.x = p[4 * i] * inv; q.y = p[4 * i + 1] * inv;
        q.z = p[4 * i + 2] * inv; q.w = p[4 * i + 3] * inv;
        *(float4*)(outrow + off) = q;
        float4 ta = *(const float4*)(t0 + off);
        float4 tb = *(const float4*)(t0 + MMM + off);
        float4 tc = *(const float4*)(t0 + 2 * MMM + off);
        w0 += q.x * ta.x + q.y * ta.y + q.z * ta.z + q.w * ta.w;
        w1 += q.x * tb.x + q.y * tb.y + q.z * tb.z + q.w * tb.w;
        w2 += q.x * tc.x + q.y * tc.y + q.z * tc.z + q.w * tc.w;
    }
#pragma unroll
    for (int o = 16; o > 0; o >>= 1) {
        w0 += __shfl_xor_sync(0xffffffffu, w0, o);
        w1 += __shfl_xor_sync(0xffffffffu, w1, o);
        w2 += __shfl_xor_sync(0xffffffffu, w2, o);
    }
    if (lane == 0) {
        g_weights[gw] = sum;
        g_wt[(size_t)bb * 3 * NN + n]          = w0;
        g_wt[(size_t)bb * 3 * NN + NN + n]     = w1;
        g_wt[(size_t)bb * 3 * NN + 2 * NN + n] = w2;
    }
}

// ---------------- per-batch Procrustes (double precision 3x3 SVD) ----------------
__device__ double block_reduce_d(double v, double* sred, int tid) {
    sred[tid] = v; __syncthreads();
    for (int s = 128; s > 0; s >>= 1) {
        if (tid < s) sred[tid] += sred[tid + s];
        __syncthreads();
    }
    double r = sred[0]; __syncthreads();
    return r;
}

__global__ __launch_bounds__(256) void procrustes_kernel(const float* __restrict__ src,
                                                         float* __restrict__ out) {
    const int bb = blockIdx.x, tid = threadIdx.x;
    __shared__ double sred[256];
    __shared__ double bc[16];

    const float* w  = g_weights + bb * NN;
    const float* wt = g_wt + (size_t)bb * 3 * NN;
    const float* sp = src + (size_t)bb * 3 * NN;

    double lv = 0.0;
    for (int n = tid; n < NN; n += 256) lv += (double)w[n];
    double wsum = block_reduce_d(lv, sred, tid);
    double denom = wsum + 1e-8;

    double acc[6] = {0, 0, 0, 0, 0, 0};
    for (int n = tid; n < NN; n += 256) {
        double wn = (double)w[n] / denom;
        acc[0] += (double)sp[n] * wn;
        acc[1] += (double)sp[NN + n] * wn;
        acc[2] += (double)sp[2 * NN + n] * wn;
        acc[3] += (double)wt[n] * wn;
        acc[4] += (double)wt[NN + n] * wn;
        acc[5] += (double)wt[2 * NN + n] * wn;
    }
    for (int q = 0; q < 6; q++) {
        double r = block_reduce_d(acc[q], sred, tid);
        if (tid == 0) bc[q] = r;
    }
    __syncthreads();
    double scent[3] = {bc[0], bc[1], bc[2]};
    double tcent[3] = {bc[3], bc[4], bc[5]};

    double h[9] = {0, 0, 0, 0, 0, 0, 0, 0, 0};
    for (int n = tid; n < NN; n += 256) {
        double wn = (double)w[n] / denom;
        double si[3] = {(double)sp[n] - scent[0],
                        (double)sp[NN + n] - scent[1],
                        (double)sp[2 * NN + n] - scent[2]};
        double tj[3] = {((double)wt[n] - tcent[0]) * wn,
                        ((double)wt[NN + n] - tcent[1]) * wn,
                        ((double)wt[2 * NN + n] - tcent[2]) * wn};
#pragma unroll
        for (int i = 0; i < 3; i++)
#pragma unroll
            for (int j = 0; j < 3; j++) h[i * 3 + j] += si[i] * tj[j];
    }
    for (int q = 0; q < 9; q++) {
        double r = block_reduce_d(h[q], sred, tid);
        if (tid == 0) bc[q] = r;
    }
    __syncthreads();

    if (tid == 0) {
        double H[3][3];
        for (int i = 0; i < 3; i++)
            for (int j = 0; j < 3; j++) H[i][j] = bc[i * 3 + j];
        double A[3][3];
        for (int i = 0; i < 3; i++)
            for (int j = 0; j < 3; j++)
                A[i][j] = H[0][i] * H[0][j] + H[1][i] * H[1][j] + H[2][i] * H[2][j];
        double V[3][3] = {{1, 0, 0}, {0, 1, 0}, {0, 0, 1}};
        for (int sweep = 0; sweep < 45; sweep++) {
            int r3 = sweep % 3;
            int p = (r3 == 2) ? 1 : 0;
            int q = (r3 == 0) ? 1 : 2;
            double apq = A[p][q];
            if (fabs(apq) < 1e-280) continue;
            double theta = (A[q][q] - A[p][p]) / (2.0 * apq);
            double tt = copysign(1.0, theta) / (fabs(theta) + sqrt(theta * theta + 1.0));
            double cc = 1.0 / sqrt(tt * tt + 1.0);
            double ssn = tt * cc;
            for (int k = 0; k < 3; k++) {
                double akp = A[k][p], akq = A[k][q];
                A[k][p] = cc * akp - ssn * akq;
                A[k][q] = ssn * akp + cc * akq;
            }
            for (int k = 0; k < 3; k++) {
                double apk = A[p][k], aqk = A[q][k];
                A[p][k] = cc * apk - ssn * aqk;
                A[q][k] = ssn * apk + cc * aqk;
            }
            for (int k = 0; k < 3; k++) {
                double vkp = V[k][p], vkq = V[k][q];
                V[k][p] = cc * vkp - ssn * vkq;
                V[k][q] = ssn * vkp + cc * vkq;
            }
        }
        double ev[3] = {A[0][0], A[1][1], A[2][2]};
        int idx[3] = {0, 1, 2};
        if (ev[idx[0]] < ev[idx[1]]) { int t2 = idx[0]; idx[0] = idx[1]; idx[1] = t2; }
        if (ev[idx[0]] < ev[idx[2]]) { int t2 = idx[0]; idx[0] = idx[2]; idx[2] = t2; }
        if (ev[idx[1]] < ev[idx[2]]) { int t2 = idx[1]; idx[1] = idx[2]; idx[2] = t2; }

        double Vs[3][3], U[3][3];
        for (int k = 0; k < 3; k++) {
            int c = idx[k];
            double sv = sqrt(fmax(ev[c], 0.0));
            double invs = (sv > 1e-30) ? 1.0 / sv : 0.0;
            for (int i = 0; i < 3; i++) Vs[i][k] = V[i][c];
            for (int i = 0; i < 3; i++)
                U[i][k] = (H[i][0] * V[0][c] + H[i][1] * V[1][c] + H[i][2] * V[2][c]) * invs;
        }
        double detH = H[0][0] * (H[1][1] * H[2][2] - H[1][2] * H[2][1])
                    - H[0][1] * (H[1][0] * H[2][2] - H[1][2] * H[2][0])
                    + H[0][2] * (H[1][0] * H[2][1] - H[1][1] * H[2][0]);
        double dsg = (detH >= 0.0) ? 1.0 : -1.0;
        double R[3][3];
        for (int i = 0; i < 3; i++)
            for (int j = 0; j < 3; j++)
                R[i][j] = Vs[i][0] * U[j][0] + Vs[i][1] * U[j][1] + dsg * Vs[i][2] * U[j][2];
        double tv[3];
        for (int i = 0; i < 3; i++)
            tv[i] = -(R[i][0] * scent[0] + R[i][1] * scent[1] + R[i][2] * scent[2]) + tcent[i];

        for (int i = 0; i < 3; i++)
            for (int j = 0; j < 3; j++)
                out[bb * 9 + i * 3 + j] = (float)R[i][j];
        for (int i = 0; i < 3; i++)
            out[BB * 9 + bb * 3 + i] = (float)tv[i];
    }
}

// ---------------- launch ----------------
extern "C" void kernel_launch(void* const* d_in, const int* in_sizes, int n_in,
                              void* d_out, int out_size) {
    const float* src_emb = (const float*)d_in[0];
    const float* tgt_emb = (const float*)d_in[1];
    const float* src     = (const float*)d_in[2];
    const float* tgt     = (const float*)d_in[3];
    const float* temp    = (const float*)d_in[4];
    float* out = (float*)d_out;
    float* out_pn = out + BB * 9 + BB * 3;

    init_kernel<<<64, 256>>>();
    convert_kernel<<<dim3(NN / 32, DKK / 32, 2 * BB), dim3(32, 8)>>>(src_emb, tgt_emb);

    const int gemm_smem = 2 * STAGE_BYTES;   // 81920 B (epilogue reuses 67584 B of it)
    cudaFuncSetAttribute(gemm_mma, cudaFuncAttributeMaxDynamicSharedMemorySize, gemm_smem);
    gemm_mma<<<dim3(MMM / 128, NN / 128, BB), 256, gemm_smem>>>(temp);

    for (int it = 0; it < 5; it++) {
        row_kernel<<<(BB * NN) / 8, 256>>>();
        colreduce_kernel<<<(BB * MMM) / 256, 256>>>();
    }
    final_kernel<<<(BB * NN) / 8, 256>>>(tgt, out_pn);
    procrustes_kernel<<<BB, 256>>>(src, out);
}

// round 5
// speedup vs baseline: 1.6613x; 1.0035x over previous
#include <cuda_runtime.h>
#include <cuda_bf16.h>
#include <math.h>
#include <stdint.h>

#define BB 16
#define DKK 512
#define NN 1024
#define MMM 1024

// ---------------- scratch (device globals) ----------------
__device__ float g_scores[(size_t)BB * NN * MMM];          // affinity, 64 MB (written once by GEMM)
__device__ __nv_bfloat16 g_shi[(size_t)BB * NN * DKK];     // src hi, transposed [b][n][d]
__device__ __nv_bfloat16 g_slo[(size_t)BB * NN * DKK];
__device__ __nv_bfloat16 g_thi[(size_t)BB * MMM * DKK];    // tgt hi, transposed [b][m][d]
__device__ __nv_bfloat16 g_tlo[(size_t)BB * MMM * DKK];
__device__ float g_cp[(size_t)BB * 128 * MMM];             // column partial sums, 8 MB
__device__ float g_r[BB * NN];                             // row duals (cumulative)
__device__ float g_c[BB * MMM];                            // col duals (cumulative)
__device__ float g_weights[BB * NN];
__device__ float g_wt[BB * 3 * NN];

// ---------------- PTX helpers (sm_80-class only) ----------------
__device__ __forceinline__ uint32_t smem_u32(const void* p) {
    uint32_t a;
    asm("{ .reg .u64 t; cvta.to.shared.u64 t, %1; cvt.u32.u64 %0, t; }" : "=r"(a) : "l"(p));
    return a;
}
#define LDSM4(r0, r1, r2, r3, addr) \
    asm volatile("ldmatrix.sync.aligned.m8n8.x4.shared.b16 {%0,%1,%2,%3}, [%4];" \
        : "=r"(r0), "=r"(r1), "=r"(r2), "=r"(r3) : "r"(addr))
#define MMA16816(c, a, b0, b1) \
    asm volatile("mma.sync.aligned.m16n8k16.row.col.f32.bf16.bf16.f32 " \
        "{%0,%1,%2,%3}, {%4,%5,%6,%7}, {%8,%9}, {%0,%1,%2,%3};" \
        : "+f"((c)[0]), "+f"((c)[1]), "+f"((c)[2]), "+f"((c)[3]) \
        : "r"((a)[0]), "r"((a)[1]), "r"((a)[2]), "r"((a)[3]), "r"(b0), "r"(b1))
#define CPASYNC16(saddr, gptr) \
    asm volatile("cp.async.cg.shared.global [%0], [%1], 16;" :: "r"(saddr), "l"(gptr))
#define CP_COMMIT() asm volatile("cp.async.commit_group;" ::: "memory")
#define CP_WAIT1()  asm volatile("cp.async.wait_group 1;" ::: "memory")
#define CP_WAIT0()  asm volatile("cp.async.wait_group 0;" ::: "memory")

// 32-byte L2-resident load/store (hint requires v8.b32 form on this target)
__device__ __forceinline__ void ldg_evl8(const float* p, float4& v0, float4& v1) {
    uint32_t r0, r1, r2, r3, r4, r5, r6, r7;
    asm volatile("ld.global.L2::evict_last.v8.b32 {%0,%1,%2,%3,%4,%5,%6,%7}, [%8];"
                 : "=r"(r0), "=r"(r1), "=r"(r2), "=r"(r3),
                   "=r"(r4), "=r"(r5), "=r"(r6), "=r"(r7) : "l"(p));
    v0.x = __uint_as_float(r0); v0.y = __uint_as_float(r1);
    v0.z = __uint_as_float(r2); v0.w = __uint_as_float(r3);
    v1.x = __uint_as_float(r4); v1.y = __uint_as_float(r5);
    v1.z = __uint_as_float(r6); v1.w = __uint_as_float(r7);
}
__device__ __forceinline__ void stg_evl8(float* p, float4 v0, float4 v1) {
    asm volatile("st.global.L2::evict_last.v8.b32 [%0], {%1,%2,%3,%4,%5,%6,%7,%8};"
                 :: "l"(p),
                    "r"(__float_as_uint(v0.x)), "r"(__float_as_uint(v0.y)),
                    "r"(__float_as_uint(v0.z)), "r"(__float_as_uint(v0.w)),
                    "r"(__float_as_uint(v1.x)), "r"(__float_as_uint(v1.y)),
                    "r"(__float_as_uint(v1.z)), "r"(__float_as_uint(v1.w)) : "memory");
}

// ---------------- init: zero column duals ----------------
__global__ void init_kernel() {
    int i = blockIdx.x * blockDim.x + threadIdx.x;
    if (i < BB * MMM) g_c[i] = 0.0f;
}

// ---------------- transpose + hi/lo bf16 split ----------------
__global__ __launch_bounds__(256) void convert_kernel(const float* __restrict__ srcE,
                                                      const float* __restrict__ tgtE) {
    __shared__ float s[32][33];
    const int z = blockIdx.z;
    const int bb = z & 15;
    const float* in = (z < 16) ? srcE : tgtE;
    __nv_bfloat16* hi = (z < 16) ? g_shi : g_thi;
    __nv_bfloat16* lo = (z < 16) ? g_slo : g_tlo;
    const int tx = threadIdx.x, ty = threadIdx.y;   // (32, 8)
    const int n = blockIdx.x * 32 + tx;
    const int d0 = blockIdx.y * 32;
#pragma unroll
    for (int j = 0; j < 4; j++)
        s[ty + 8 * j][tx] = in[((size_t)bb * DKK + d0 + ty + 8 * j) * NN + n];
    __syncthreads();
    const int dd = d0 + tx;
#pragma unroll
    for (int j = 0; j < 4; j++) {
        int nn = blockIdx.x * 32 + ty + 8 * j;
        float v = s[tx][ty + 8 * j];
        __nv_bfloat16 h = __float2bfloat16(v);
        float rem = v - __bfloat162float(h);
        size_t o = ((size_t)bb * NN + nn) * DKK + dd;
        hi[o] = h;
        lo[o] = __float2bfloat16(rem);
    }
}

// ---------------- bf16-split GEMM via mma.sync ----------------
#define STAGE_BYTES 40960
#define ROWB 80

__global__ __launch_bounds__(256, 2) void gemm_mma(const float* __restrict__ temp) {
    extern __shared__ char sm_[];
    const uint32_t sb = smem_u32(sm_);
    const int tid = threadIdx.x, wid = tid >> 5, lane = tid & 31;
    const int mt = blockIdx.x, nt = blockIdx.y, bb = blockIdx.z;
    const int warp_m = wid & 1;     // 2 warps over 128 rows (64 each)
    const int warp_n = wid >> 1;    // 4 warps over 128 cols (32 each)

    const __nv_bfloat16* Ah = g_shi + ((size_t)bb * NN + nt * 128) * DKK;
    const __nv_bfloat16* Al = g_slo + ((size_t)bb * NN + nt * 128) * DKK;
    const __nv_bfloat16* Bh = g_thi + ((size_t)bb * MMM + mt * 128) * DKK;
    const __nv_bfloat16* Bl = g_tlo + ((size_t)bb * MMM + mt * 128) * DKK;

    auto stage_load = [&](int kc, int s) {
#pragma unroll
        for (int i = 0; i < 8; i++) {
            int q = tid + i * 256;
            int mat = q >> 9;          // 0..3: Ahi,Alo,Bhi,Blo
            int w = q & 511;
            int row = w >> 2, c = w & 3;
            const __nv_bfloat16* base =
                (mat < 2) ? ((mat == 0) ? Ah : Al) : ((mat == 2) ? Bh : Bl);
            uint32_t saddr = sb + s * STAGE_BYTES + mat * 10240 + row * ROWB + c * 16;
            const char* g = (const char*)(base + (size_t)row * DKK + kc * 32 + c * 8);
            CPASYNC16(saddr, g);
        }
        CP_COMMIT();
    };

    float acc[4][4][4];
#pragma unroll
    for (int i = 0; i < 4; i++)
#pragma unroll
        for (int j = 0; j < 4; j++)
#pragma unroll
            for (int k = 0; k < 4; k++) acc[i][j][k] = 0.0f;

    stage_load(0, 0);

    for (int kc = 0; kc < 16; kc++) {
        const int s = kc & 1;
        if (kc + 1 < 16) { stage_load(kc + 1, s ^ 1); CP_WAIT1(); }
        else             { CP_WAIT0(); }
        __syncthreads();

        const uint32_t Abase = sb + s * STAGE_BYTES + (warp_m * 64) * ROWB;
        const uint32_t Bbase = sb + s * STAGE_BYTES + 20480 + (warp_n * 32) * ROWB;

#pragma unroll
        for (int h = 0; h < 2; h++) {
            uint32_t ah[4][4], al[4][4], bh[2][4], bl[2][4];
            uint32_t adv[4];
#pragma unroll
            for (int m4 = 0; m4 < 4; m4++) {
                adv[m4] = Abase + (uint32_t)((m4 * 16 + (lane & 15)) * ROWB
                          + (h * 2 + (lane >> 4)) * 16);
                LDSM4(ah[m4][0], ah[m4][1], ah[m4][2], ah[m4][3], adv[m4]);
            }
#pragma unroll
            for (int np = 0; np < 2; np++) {
                uint32_t bd = Bbase + (uint32_t)((np * 16 + ((lane >> 4) & 1) * 8 + (lane & 7)) * ROWB
                             + (h * 2 + ((lane >> 3) & 1)) * 16);
                LDSM4(bh[np][0], bh[np][1], bh[np][2], bh[np][3], bd);
                LDSM4(bl[np][0], bl[np][1], bl[np][2], bl[np][3], bd + 10240);
            }
            // hi*hi
#pragma unroll
            for (int m4 = 0; m4 < 4; m4++)
#pragma unroll
                for (int n8 = 0; n8 < 4; n8++) {
                    const int np = n8 >> 1, hf = (n8 & 1) * 2;
                    MMA16816(acc[m4][n8], ah[m4], bh[np][hf], bh[np][hf + 1]);
                }
            // load A-lo (latency hidden under hi*lo MMAs)
#pragma unroll
            for (int m4 = 0; m4 < 4; m4++)
                LDSM4(al[m4][0], al[m4][1], al[m4][2], al[m4][3], adv[m4] + 10240);
            // hi*lo
#pragma unroll
            for (int m4 = 0; m4 < 4; m4++)
#pragma unroll
                for (int n8 = 0; n8 < 4; n8++) {
                    const int np = n8 >> 1, hf = (n8 & 1) * 2;
                    MMA16816(acc[m4][n8], ah[m4], bl[np][hf], bl[np][hf + 1]);
                }
            // lo*hi
#pragma unroll
            for (int m4 = 0; m4 < 4; m4++)
#pragma unroll
                for (int n8 = 0; n8 < 4; n8++) {
                    const int np = n8 >> 1, hf = (n8 & 1) * 2;
                    MMA16816(acc[m4][n8], al[m4], bh[np][hf], bh[np][hf + 1]);
                }
        }
        __syncthreads();
    }

    // ---- epilogue: stage through smem (132-float padded rows), coalesced 32B stores ----
    float* smF = (float*)sm_;
#pragma unroll
    for (int m4 = 0; m4 < 4; m4++)
#pragma unroll
        for (int n8 = 0; n8 < 4; n8++) {
            int r0 = warp_m * 64 + m4 * 16 + (lane >> 2);
            int col = warp_n * 32 + n8 * 8 + (lane & 3) * 2;
            *(float2*)(smF + r0 * 132 + col)       = make_float2(acc[m4][n8][0], acc[m4][n8][1]);
            *(float2*)(smF + (r0 + 8) * 132 + col) = make_float2(acc[m4][n8][2], acc[m4][n8][3]);
        }
    __syncthreads();

    const float alpha = rsqrtf((float)DKK) / temp[bb];
    float* C = g_scores + (size_t)bb * NN * MMM + (size_t)(nt * 128) * MMM + mt * 128;
#pragma unroll
    for (int i = 0; i < 8; i++) {
        int idx = tid + i * 256;            // 0..2047 chunks of 8 floats
        int row = idx >> 4, c8 = idx & 15;
        const float* sp = smF + row * 132 + c8 * 8;
        float4 v0 = *(const float4*)sp;
        float4 v1 = *(const float4*)(sp + 4);
        v0.x *= alpha; v0.y *= alpha; v0.z *= alpha; v0.w *= alpha;
        v1.x *= alpha; v1.y *= alpha; v1.z *= alpha; v1.w *= alpha;
        stg_evl8(C + (size_t)row * MMM + c8 * 8, v0, v1);   // keep scores L2-resident
    }
}

// ---------------- row pass: r[n] = LSE_m(aff - c, 0); emit column exp-partials ----------------
__global__ __launch_bounds__(256) void row_kernel() {
    __shared__ float s_p[8][1024];
    __shared__ float s_scale[8];
    const int w    = threadIdx.x >> 5;
    const int lane = threadIdx.x & 31;
    const int gw   = blockIdx.x * 8 + w;
    const int bb   = gw >> 10;
    const float* aff = g_scores + (size_t)gw * MMM;
    const float* c   = g_c + bb * MMM;

    // pass A: x = aff - c -> smem, track max (32B hinted loads keep scores in L2)
    float mx = 0.0f;    // slack term included
#pragma unroll
    for (int i = 0; i < 4; i++) {
        int off = i * 256 + lane * 8;
        float4 a0, a1;
        ldg_evl8(aff + off, a0, a1);
        float4 c0 = *(const float4*)(c + off);
        float4 c1 = *(const float4*)(c + off + 4);
        float4 x0, x1;
        x0.x = a0.x - c0.x; x0.y = a0.y - c0.y; x0.z = a0.z - c0.z; x0.w = a0.w - c0.w;
        x1.x = a1.x - c1.x; x1.y = a1.y - c1.y; x1.z = a1.z - c1.z; x1.w = a1.w - c1.w;
        *(float4*)(&s_p[w][off])     = x0;
        *(float4*)(&s_p[w][off + 4]) = x1;
        mx = fmaxf(mx, fmaxf(fmaxf(x0.x, x0.y), fmaxf(x0.z, x0.w)));
        mx = fmaxf(mx, fmaxf(fmaxf(x1.x, x1.y), fmaxf(x1.z, x1.w)));
    }
#pragma unroll
    for (int o = 16; o > 0; o >>= 1) mx = fmaxf(mx, __shfl_xor_sync(0xffffffffu, mx, o));

    // pass B: exp in place, sum
    float s = 0.0f;
#pragma unroll
    for (int i = 0; i < 8; i++) {
        int off = i * 128 + lane * 4;
        float4 x = *(const float4*)(&s_p[w][off]);
        float4 e;
        e.x = __expf(x.x - mx); e.y = __expf(x.y - mx);
        e.z = __expf(x.z - mx); e.w = __expf(x.w - mx);
        *(float4*)(&s_p[w][off]) = e;
        s += e.x + e.y + e.z + e.w;
    }
#pragma unroll
    for (int o = 16; o > 0; o >>= 1) s += __shfl_xor_sync(0xffffffffu, s, o);
    s += __expf(-mx);                    // slack

    const float r = mx + logf(s);
    if (lane == 0) {
        g_r[gw] = r;
        s_scale[w] = __expf(mx - r);     // = 1/s
    }
    __syncthreads();

    const int t = threadIdx.x;
    float4 acc = make_float4(0.f, 0.f, 0.f, 0.f);
#pragma unroll
    for (int ww = 0; ww < 8; ww++) {
        float sc = s_scale[ww];
        float4 v = *(const float4*)(&s_p[ww][t * 4]);
        acc.x += v.x * sc; acc.y += v.y * sc; acc.z += v.z * sc; acc.w += v.w * sc;
    }
    const int rb = blockIdx.x & 127;
    *(float4*)(g_cp + ((size_t)(bb * 128 + rb)) * 1024 + t * 4) = acc;
}

// ---------------- column reduce: c = c_old + log(S + exp(-c_old)) ----------------
__global__ __launch_bounds__(256) void colreduce_kernel() {
    const int idx = blockIdx.x * 256 + threadIdx.x;   // < 16384
    const int b = idx >> 10, m = idx & 1023;
    const float* cp = g_cp + (size_t)b * 128 * 1024 + m;
    float S = 0.0f;
#pragma unroll 8
    for (int rb = 0; rb < 128; rb++) S += cp[(size_t)rb * 1024];
    const float co = g_c[idx];
    g_c[idx] = co + logf(S + __expf(-co));
}

// ---------------- final: perm_norm, weights, weighted_tgt ----------------
__global__ __launch_bounds__(256) void final_kernel(const float* __restrict__ tgt,
                                                    float* __restrict__ out_pn) {
    const int gw   = (blockIdx.x * 256 + threadIdx.x) >> 5;
    const int lane = threadIdx.x & 31;
    const int bb   = gw >> 10;
    const int n    = gw & 1023;
    const float* aff = g_scores + (size_t)gw * MMM;
    const float* c   = g_c + bb * MMM;
    const float r    = g_r[gw];

    float p[32];
    float sum = 0.0f;
#pragma unroll
    for (int i = 0; i < 8; i++) {
        int off = i * 128 + lane * 4;
        float4 a = *(const float4*)(aff + off);
        float4 cc = *(const float4*)(c + off);
        float p0 = __expf(a.x - cc.x - r), p1 = __expf(a.y - cc.y - r);
        float p2 = __expf(a.z - cc.z - r), p3 = __expf(a.w - cc.w - r);
        p[4 * i] = p0; p[4 * i + 1] = p1; p[4 * i + 2] = p2; p[4 * i + 3] = p3;
        sum += p0 + p1 + p2 + p3;
    }
#pragma unroll
    for (int o = 16; o > 0; o >>= 1) sum += __shfl_xor_sync(0xffffffffu, sum, o);

    const float inv = 1.0f / (sum + 1e-8f);
    const float* t0 = tgt + (size_t)bb * 3 * MMM;
    float w0 = 0.0f, w1 = 0.0f, w2 = 0.0f;
    float* outrow = out_pn + (size_t)gw * MMM;
#pragma unroll
    for (int i = 0; i < 8; i++) {
        int off = i * 128 + lane * 4;
        float4 q;
        q.x = p[4 * i] * inv; q.y = p[4 * i + 1] * inv;
        q.z = p[4 * i + 2] * inv; q.w = p[4 * i + 3] * inv;
        __stcs((float4*)(outrow + off), q);   // streaming store
        float4 ta = *(const float4*)(t0 + off);
        float4 tb = *(const float4*)(t0 + MMM + off);
        float4 tc = *(const float4*)(t0 + 2 * MMM + off);
        w0 += q.x * ta.x + q.y * ta.y + q.z * ta.z + q.w * ta.w;
        w1 += q.x * tb.x + q.y * tb.y + q.z * tb.z + q.w * tb.w;
        w2 += q.x * tc.x + q.y * tc.y + q.z * tc.z + q.w * tc.w;
    }
#pragma unroll
    for (int o = 16; o > 0; o >>= 1) {
        w0 += __shfl_xor_sync(0xffffffffu, w0, o);
        w1 += __shfl_xor_sync(0xffffffffu, w1, o);
        w2 += __shfl_xor_sync(0xffffffffu, w2, o);
    }
    if (lane == 0) {
        g_weights[gw] = sum;
        g_wt[(size_t)bb * 3 * NN + n]          = w0;
        g_wt[(size_t)bb * 3 * NN + NN + n]     = w1;
        g_wt[(size_t)bb * 3 * NN + 2 * NN + n] = w2;
    }
}

// ---------------- per-batch Procrustes (double precision 3x3 SVD) ----------------
__device__ double block_reduce_d(double v, double* sred, int tid) {
    sred[tid] = v; __syncthreads();
    for (int s = 128; s > 0; s >>= 1) {
        if (tid < s) sred[tid] += sred[tid + s];
        __syncthreads();
    }
    double r = sred[0]; __syncthreads();
    return r;
}

__global__ __launch_bounds__(256) void procrustes_kernel(const float* __restrict__ src,
                                                         float* __restrict__ out) {
    const int bb = blockIdx.x, tid = threadIdx.x;
    __shared__ double sred[256];
    __shared__ double bc[16];

    const float* w  = g_weights + bb * NN;
    const float* wt = g_wt + (size_t)bb * 3 * NN;
    const float* sp = src + (size_t)bb * 3 * NN;

    double lv = 0.0;
    for (int n = tid; n < NN; n += 256) lv += (double)w[n];
    double wsum = block_reduce_d(lv, sred, tid);
    double denom = wsum + 1e-8;

    double acc[6] = {0, 0, 0, 0, 0, 0};
    for (int n = tid; n < NN; n += 256) {
        double wn = (double)w[n] / denom;
        acc[0] += (double)sp[n] * wn;
        acc[1] += (double)sp[NN + n] * wn;
        acc[2] += (double)sp[2 * NN + n] * wn;
        acc[3] += (double)wt[n] * wn;
        acc[4] += (double)wt[NN + n] * wn;
        acc[5] += (double)wt[2 * NN + n] * wn;
    }
    for (int q = 0; q < 6; q++) {
        double r = block_reduce_d(acc[q], sred, tid);
        if (tid == 0) bc[q] = r;
    }
    __syncthreads();
    double scent[3] = {bc[0], bc[1], bc[2]};
    double tcent[3] = {bc[3], bc[4], bc[5]};

    double h[9] = {0, 0, 0, 0, 0, 0, 0, 0, 0};
    for (int n = tid; n < NN; n += 256) {
        double wn = (double)w[n] / denom;
        double si[3] = {(double)sp[n] - scent[0],
                        (double)sp[NN + n] - scent[1],
                        (double)sp[2 * NN + n] - scent[2]};
        double tj[3] = {((double)wt[n] - tcent[0]) * wn,
                        ((double)wt[NN + n] - tcent[1]) * wn,
                        ((double)wt[2 * NN + n] - tcent[2]) * wn};
#pragma unroll
        for (int i = 0; i < 3; i++)
#pragma unroll
            for (int j = 0; j < 3; j++) h[i * 3 + j] += si[i] * tj[j];
    }
    for (int q = 0; q < 9; q++) {
        double r = block_reduce_d(h[q], sred, tid);
        if (tid == 0) bc[q] = r;
    }
    __syncthreads();

    if (tid == 0) {
        double H[3][3];
        for (int i = 0; i < 3; i++)
            for (int j = 0; j < 3; j++) H[i][j] = bc[i * 3 + j];
        double A[3][3];
        for (int i = 0; i < 3; i++)
            for (int j = 0; j < 3; j++)
                A[i][j] = H[0][i] * H[0][j] + H[1][i] * H[1][j] + H[2][i] * H[2][j];
        double V[3][3] = {{1, 0, 0}, {0, 1, 0}, {0, 0, 1}};
        for (int sweep = 0; sweep < 45; sweep++) {
            int r3 = sweep % 3;
            int p = (r3 == 2) ? 1 : 0;
            int q = (r3 == 0) ? 1 : 2;
            double apq = A[p][q];
            if (fabs(apq) < 1e-280) continue;
            double theta = (A[q][q] - A[p][p]) / (2.0 * apq);
            double tt = copysign(1.0, theta) / (fabs(theta) + sqrt(theta * theta + 1.0));
            double cc = 1.0 / sqrt(tt * tt + 1.0);
            double ssn = tt * cc;
            for (int k = 0; k < 3; k++) {
                double akp = A[k][p], akq = A[k][q];
                A[k][p] = cc * akp - ssn * akq;
                A[k][q] = ssn * akp + cc * akq;
            }
            for (int k = 0; k < 3; k++) {
                double apk = A[p][k], aqk = A[q][k];
                A[p][k] = cc * apk - ssn * aqk;
                A[q][k] = ssn * apk + cc * aqk;
            }
            for (int k = 0; k < 3; k++) {
                double vkp = V[k][p], vkq = V[k][q];
                V[k][p] = cc * vkp - ssn * vkq;
                V[k][q] = ssn * vkp + cc * vkq;
            }
        }
        double ev[3] = {A[0][0], A[1][1], A[2][2]};
        int idx[3] = {0, 1, 2};
        if (ev[idx[0]] < ev[idx[1]]) { int t2 = idx[0]; idx[0] = idx[1]; idx[1] = t2; }
        if (ev[idx[0]] < ev[idx[2]]) { int t2 = idx[0]; idx[0] = idx[2]; idx[2] = t2; }
        if (ev[idx[1]] < ev[idx[2]]) { int t2 = idx[1]; idx[1] = idx[2]; idx[2] = t2; }

        double Vs[3][3], U[3][3];
        for (int k = 0; k < 3; k++) {
            int c = idx[k];
            double sv = sqrt(fmax(ev[c], 0.0));
            double invs = (sv > 1e-30) ? 1.0 / sv : 0.0;
            for (int i = 0; i < 3; i++) Vs[i][k] = V[i][c];
            for (int i = 0; i < 3; i++)
                U[i][k] = (H[i][0] * V[0][c] + H[i][1] * V[1][c] + H[i][2] * V[2][c]) * invs;
        }
        double detH = H[0][0] * (H[1][1] * H[2][2] - H[1][2] * H[2][1])
                    - H[0][1] * (H[1][0] * H[2][2] - H[1][2] * H[2][0])
                    + H[0][2] * (H[1][0] * H[2][1] - H[1][1] * H[2][0]);
        double dsg = (detH >= 0.0) ? 1.0 : -1.0;
        double R[3][3];
        for (int i = 0; i < 3; i++)
            for (int j = 0; j < 3; j++)
                R[i][j] = Vs[i][0] * U[j][0] + Vs[i][1] * U[j][1] + dsg * Vs[i][2] * U[j][2];
        double tv[3];
        for (int i = 0; i < 3; i++)
            tv[i] = -(R[i][0] * scent[0] + R[i][1] * scent[1] + R[i][2] * scent[2]) + tcent[i];

        for (int i = 0; i < 3; i++)
            for (int j = 0; j < 3; j++)
                out[bb * 9 + i * 3 + j] = (float)R[i][j];
        for (int i = 0; i < 3; i++)
            out[BB * 9 + bb * 3 + i] = (float)tv[i];
    }
}

// ---------------- launch ----------------
extern "C" void kernel_launch(void* const* d_in, const int* in_sizes, int n_in,
                              void* d_out, int out_size) {
    const float* src_emb = (const float*)d_in[0];
    const float* tgt_emb = (const float*)d_in[1];
    const float* src     = (const float*)d_in[2];
    const float* tgt     = (const float*)d_in[3];
    const float* temp    = (const float*)d_in[4];
    float* out = (float*)d_out;
    float* out_pn = out + BB * 9 + BB * 3;

    init_kernel<<<64, 256>>>();
    convert_kernel<<<dim3(NN / 32, DKK / 32, 2 * BB), dim3(32, 8)>>>(src_emb, tgt_emb);

    const int gemm_smem = 2 * STAGE_BYTES;   // 81920 B per CTA; 2 CTAs/SM
    cudaFuncSetAttribute(gemm_mma, cudaFuncAttributeMaxDynamicSharedMemorySize, gemm_smem);
    gemm_mma<<<dim3(MMM / 128, NN / 128, BB), 256, gemm_smem>>>(temp);

    for (int it = 0; it < 5; it++) {
        row_kernel<<<(BB * NN) / 8, 256>>>();
        colreduce_kernel<<<(BB * MMM) / 256, 256>>>();
    }
    final_kernel<<<(BB * NN) / 8, 256>>>(tgt, out_pn);
    procrustes_kernel<<<BB, 256>>>(src, out);
}

// round 6
// speedup vs baseline: 1.7542x; 1.0559x over previous
#include <cuda_runtime.h>
#include <cuda_bf16.h>
#include <math.h>
#include <stdint.h>

#define BB 16
#define DKK 512
#define NN 1024
#define MMM 1024

// ---------------- scratch (device globals) ----------------
__device__ float g_scores[(size_t)BB * NN * MMM];          // affinity, 64 MB (written once by GEMM)
__device__ __nv_bfloat16 g_shi[(size_t)BB * NN * DKK];     // src hi, transposed [b][n][d]
__device__ __nv_bfloat16 g_slo[(size_t)BB * NN * DKK];
__device__ __nv_bfloat16 g_thi[(size_t)BB * MMM * DKK];    // tgt hi, transposed [b][m][d]
__device__ __nv_bfloat16 g_tlo[(size_t)BB * MMM * DKK];
__device__ float g_cp[(size_t)BB * 128 * MMM];             // column partial sums, 8 MB
__device__ float g_r[BB * NN];                             // row duals (cumulative)
__device__ float g_c[BB * MMM];                            // col duals (cumulative)
__device__ float g_weights[BB * NN];
__device__ float g_wt[BB * 3 * NN];

// ---------------- PTX helpers (sm_80-class only) ----------------
__device__ __forceinline__ uint32_t smem_u32(const void* p) {
    uint32_t a;
    asm("{ .reg .u64 t; cvta.to.shared.u64 t, %1; cvt.u32.u64 %0, t; }" : "=r"(a) : "l"(p));
    return a;
}
#define LDSM4(r0, r1, r2, r3, addr) \
    asm volatile("ldmatrix.sync.aligned.m8n8.x4.shared.b16 {%0,%1,%2,%3}, [%4];" \
        : "=r"(r0), "=r"(r1), "=r"(r2), "=r"(r3) : "r"(addr))
#define MMA16816(c, a, b0, b1) \
    asm volatile("mma.sync.aligned.m16n8k16.row.col.f32.bf16.bf16.f32 " \
        "{%0,%1,%2,%3}, {%4,%5,%6,%7}, {%8,%9}, {%0,%1,%2,%3};" \
        : "+f"((c)[0]), "+f"((c)[1]), "+f"((c)[2]), "+f"((c)[3]) \
        : "r"((a)[0]), "r"((a)[1]), "r"((a)[2]), "r"((a)[3]), "r"(b0), "r"(b1))
#define CPASYNC16(saddr, gptr) \
    asm volatile("cp.async.cg.shared.global [%0], [%1], 16;" :: "r"(saddr), "l"(gptr))
#define CP_COMMIT() asm volatile("cp.async.commit_group;" ::: "memory")
#define CP_WAIT1()  asm volatile("cp.async.wait_group 1;" ::: "memory")
#define CP_WAIT0()  asm volatile("cp.async.wait_group 0;" ::: "memory")

__device__ __forceinline__ uint32_t sw128(uint32_t off) {
    return off ^ ((off >> 3) & 0x70);
}
__device__ __forceinline__ void stg_evl8(float* p, float4 v0, float4 v1) {
    asm volatile("st.global.L2::evict_last.v8.b32 [%0], {%1,%2,%3,%4,%5,%6,%7,%8};"
                 :: "l"(p),
                    "r"(__float_as_uint(v0.x)), "r"(__float_as_uint(v0.y)),
                    "r"(__float_as_uint(v0.z)), "r"(__float_as_uint(v0.w)),
                    "r"(__float_as_uint(v1.x)), "r"(__float_as_uint(v1.y)),
                    "r"(__float_as_uint(v1.z)), "r"(__float_as_uint(v1.w)) : "memory");
}

// ---------------- init: zero column duals ----------------
__global__ void init_kernel() {
    int i = blockIdx.x * blockDim.x + threadIdx.x;
    if (i < BB * MMM) g_c[i] = 0.0f;
}

// near-noop spacer so ncu (-s 5 -c 1) lands on the GEMM launch
__global__ void dummy_kernel() {
    if (threadIdx.x == 0) g_cp[0] = 0.0f;   // overwritten by row_kernel later
}

// ---------------- transpose + hi/lo bf16 split ----------------
__global__ __launch_bounds__(256) void convert_kernel(const float* __restrict__ srcE,
                                                      const float* __restrict__ tgtE) {
    __shared__ float s[32][33];
    const int z = blockIdx.z;
    const int bb = z & 15;
    const float* in = (z < 16) ? srcE : tgtE;
    __nv_bfloat16* hi = (z < 16) ? g_shi : g_thi;
    __nv_bfloat16* lo = (z < 16) ? g_slo : g_tlo;
    const int tx = threadIdx.x, ty = threadIdx.y;   // (32, 8)
    const int n = blockIdx.x * 32 + tx;
    const int d0 = blockIdx.y * 32;
#pragma unroll
    for (int j = 0; j < 4; j++)
        s[ty + 8 * j][tx] = in[((size_t)bb * DKK + d0 + ty + 8 * j) * NN + n];
    __syncthreads();
    const int dd = d0 + tx;
#pragma unroll
    for (int j = 0; j < 4; j++) {
        int nn = blockIdx.x * 32 + ty + 8 * j;
        float v = s[tx][ty + 8 * j];
        __nv_bfloat16 h = __float2bfloat16(v);
        float rem = v - __bfloat162float(h);
        size_t o = ((size_t)bb * NN + nn) * DKK + dd;
        hi[o] = h;
        lo[o] = __float2bfloat16(rem);
    }
}

// ---------------- bf16-split GEMM via mma.sync ----------------
// 512 threads, 16 warps of 32x32; CTA tile 128x128; K chunks of 64, double buffered.
// smem stage: 4 mats (Ah,Al,Bh,Bl) x 128 rows x 128B, SW128 swizzled. 64KB/stage.
#define MAT_B 16384
#define STG_B 65536

__global__ __launch_bounds__(512, 1) void gemm_mma(const float* __restrict__ temp) {
    extern __shared__ char sm_[];
    const uint32_t sb = smem_u32(sm_);
    const int tid = threadIdx.x, wid = tid >> 5, lane = tid & 31;
    const int mt = blockIdx.x, nt = blockIdx.y, bb = blockIdx.z;
    const int warp_m = wid & 3;     // 4 warps over 128 rows (32 each)
    const int warp_n = wid >> 2;    // 4 warps over 128 cols (32 each)

    const __nv_bfloat16* Ah = g_shi + ((size_t)bb * NN + nt * 128) * DKK;
    const __nv_bfloat16* Al = g_slo + ((size_t)bb * NN + nt * 128) * DKK;
    const __nv_bfloat16* Bh = g_thi + ((size_t)bb * MMM + mt * 128) * DKK;
    const __nv_bfloat16* Bl = g_tlo + ((size_t)bb * MMM + mt * 128) * DKK;

    // 4096 16B chunks per stage, 8 per thread
    auto stage_load = [&](int kc, int s) {
#pragma unroll
        for (int i = 0; i < 8; i++) {
            int q = tid + i * 512;
            int mat = q >> 10;          // 0..3: Ahi,Alo,Bhi,Blo
            int w = q & 1023;
            int row = w >> 3, c = w & 7;
            const __nv_bfloat16* base =
                (mat < 2) ? ((mat == 0) ? Ah : Al) : ((mat == 2) ? Bh : Bl);
            uint32_t saddr = sb + s * STG_B + mat * MAT_B + sw128(row * 128 + c * 16);
            const char* g = (const char*)(base + (size_t)row * DKK + kc * 64 + c * 8);
            CPASYNC16(saddr, g);
        }
        CP_COMMIT();
    };

    float acc[2][4][4];
#pragma unroll
    for (int i = 0; i < 2; i++)
#pragma unroll
        for (int j = 0; j < 4; j++)
#pragma unroll
            for (int k = 0; k < 4; k++) acc[i][j][k] = 0.0f;

    stage_load(0, 0);

    for (int kc = 0; kc < 8; kc++) {
        const int s = kc & 1;
        if (kc + 1 < 8) { stage_load(kc + 1, s ^ 1); CP_WAIT1(); }
        else            { CP_WAIT0(); }
        __syncthreads();

        const uint32_t stg = sb + s * STG_B;

#pragma unroll
        for (int h = 0; h < 4; h++) {       // four k16 steps per 64-chunk
            uint32_t ah[2][4], al[2][4], bh[2][4], bl[2][4];
#pragma unroll
            for (int mf = 0; mf < 2; mf++) {
                uint32_t off = (uint32_t)((warp_m * 32 + mf * 16 + (lane & 15)) * 128
                              + h * 32 + (lane >> 4) * 16);
                uint32_t ad = stg + sw128(off);
                LDSM4(ah[mf][0], ah[mf][1], ah[mf][2], ah[mf][3], ad);
                LDSM4(al[mf][0], al[mf][1], al[mf][2], al[mf][3], ad + MAT_B);
            }
#pragma unroll
            for (int np = 0; np < 2; np++) {
                uint32_t off = (uint32_t)((warp_n * 32 + np * 16 + ((lane >> 4) & 1) * 8 + (lane & 7)) * 128
                              + h * 32 + ((lane >> 3) & 1) * 16);
                uint32_t bd = stg + 2 * MAT_B + sw128(off);
                LDSM4(bh[np][0], bh[np][1], bh[np][2], bh[np][3], bd);
                LDSM4(bl[np][0], bl[np][1], bl[np][2], bl[np][3], bd + MAT_B);
            }
            // hi*hi
#pragma unroll
            for (int mf = 0; mf < 2; mf++)
#pragma unroll
                for (int n8 = 0; n8 < 4; n8++) {
                    const int np = n8 >> 1, hf = (n8 & 1) * 2;
                    MMA16816(acc[mf][n8], ah[mf], bh[np][hf], bh[np][hf + 1]);
                }
            // hi*lo
#pragma unroll
            for (int mf = 0; mf < 2; mf++)
#pragma unroll
                for (int n8 = 0; n8 < 4; n8++) {
                    const int np = n8 >> 1, hf = (n8 & 1) * 2;
                    MMA16816(acc[mf][n8], ah[mf], bl[np][hf], bl[np][hf + 1]);
                }
            // lo*hi
#pragma unroll
            for (int mf = 0; mf < 2; mf++)
#pragma unroll
                for (int n8 = 0; n8 < 4; n8++) {
                    const int np = n8 >> 1, hf = (n8 & 1) * 2;
                    MMA16816(acc[mf][n8], al[mf], bh[np][hf], bh[np][hf + 1]);
                }
        }
        __syncthreads();
    }

    // ---- epilogue: stage through smem (132-float padded rows), 32B coalesced stores ----
    float* smF = (float*)sm_;
#pragma unroll
    for (int mf = 0; mf < 2; mf++)
#pragma unroll
        for (int n8 = 0; n8 < 4; n8++) {
            int r0 = warp_m * 32 + mf * 16 + (lane >> 2);
            int col = warp_n * 32 + n8 * 8 + (lane & 3) * 2;
            *(float2*)(smF + r0 * 132 + col)       = make_float2(acc[mf][n8][0], acc[mf][n8][1]);
            *(float2*)(smF + (r0 + 8) * 132 + col) = make_float2(acc[mf][n8][2], acc[mf][n8][3]);
        }
    __syncthreads();

    const float alpha = rsqrtf((float)DKK) / temp[bb];
    float* C = g_scores + (size_t)bb * NN * MMM + (size_t)(nt * 128) * MMM + mt * 128;
#pragma unroll
    for (int i = 0; i < 4; i++) {
        int idx = tid + i * 512;            // 0..2047 chunks of 8 floats
        int row = idx >> 4, c8 = idx & 15;
        const float* sp = smF + row * 132 + c8 * 8;
        float4 v0 = *(const float4*)sp;
        float4 v1 = *(const float4*)(sp + 4);
        v0.x *= alpha; v0.y *= alpha; v0.z *= alpha; v0.w *= alpha;
        v1.x *= alpha; v1.y *= alpha; v1.z *= alpha; v1.w *= alpha;
        stg_evl8(C + (size_t)row * MMM + c8 * 8, v0, v1);
    }
}

// ---------------- row pass: r[n] = LSE_m(aff - c, 0); emit column exp-partials ----------------
__global__ __launch_bounds__(256) void row_kernel() {
    __shared__ float s_p[8][1024];
    __shared__ float s_scale[8];
    const int w    = threadIdx.x >> 5;
    const int lane = threadIdx.x & 31;
    const int gw   = blockIdx.x * 8 + w;
    const int bb   = gw >> 10;
    const float* aff = g_scores + (size_t)gw * MMM;
    const float* c   = g_c + bb * MMM;

    float mx = 0.0f;    // slack term included
#pragma unroll
    for (int i = 0; i < 8; i++) {
        int off = i * 128 + lane * 4;
        float4 a = *(const float4*)(aff + off);
        float4 cc = *(const float4*)(c + off);
        float4 x;
        x.x = a.x - cc.x; x.y = a.y - cc.y; x.z = a.z - cc.z; x.w = a.w - cc.w;
        *(float4*)(&s_p[w][off]) = x;
        mx = fmaxf(mx, fmaxf(fmaxf(x.x, x.y), fmaxf(x.z, x.w)));
    }
#pragma unroll
    for (int o = 16; o > 0; o >>= 1) mx = fmaxf(mx, __shfl_xor_sync(0xffffffffu, mx, o));

    float s = 0.0f;
#pragma unroll
    for (int i = 0; i < 8; i++) {
        int off = i * 128 + lane * 4;
        float4 x = *(const float4*)(&s_p[w][off]);
        float4 e;
        e.x = __expf(x.x - mx); e.y = __expf(x.y - mx);
        e.z = __expf(x.z - mx); e.w = __expf(x.w - mx);
        *(float4*)(&s_p[w][off]) = e;
        s += e.x + e.y + e.z + e.w;
    }
#pragma unroll
    for (int o = 16; o > 0; o >>= 1) s += __shfl_xor_sync(0xffffffffu, s, o);
    s += __expf(-mx);                    // slack

    const float r = mx + logf(s);
    if (lane == 0) {
        g_r[gw] = r;
        s_scale[w] = __expf(mx - r);     // = 1/s
    }
    __syncthreads();

    const int t = threadIdx.x;
    float4 acc = make_float4(0.f, 0.f, 0.f, 0.f);
#pragma unroll
    for (int ww = 0; ww < 8; ww++) {
        float sc = s_scale[ww];
        float4 v = *(const float4*)(&s_p[ww][t * 4]);
        acc.x += v.x * sc; acc.y += v.y * sc; acc.z += v.z * sc; acc.w += v.w * sc;
    }
    const int rb = blockIdx.x & 127;
    *(float4*)(g_cp + ((size_t)(bb * 128 + rb)) * 1024 + t * 4) = acc;
}

// ---------------- column reduce: c = c_old + log(S + exp(-c_old)) ----------------
__global__ __launch_bounds__(256) void colreduce_kernel() {
    const int idx = blockIdx.x * 256 + threadIdx.x;   // < 16384
    const int b = idx >> 10, m = idx & 1023;
    const float* cp = g_cp + (size_t)b * 128 * 1024 + m;
    float S = 0.0f;
#pragma unroll 8
    for (int rb = 0; rb < 128; rb++) S += cp[(size_t)rb * 1024];
    const float co = g_c[idx];
    g_c[idx] = co + logf(S + __expf(-co));
}

// ---------------- final: perm_norm, weights, weighted_tgt ----------------
__global__ __launch_bounds__(256) void final_kernel(const float* __restrict__ tgt,
                                                    float* __restrict__ out_pn) {
    const int gw   = (blockIdx.x * 256 + threadIdx.x) >> 5;
    const int lane = threadIdx.x & 31;
    const int bb   = gw >> 10;
    const int n    = gw & 1023;
    const float* aff = g_scores + (size_t)gw * MMM;
    const float* c   = g_c + bb * MMM;
    const float r    = g_r[gw];

    float p[32];
    float sum = 0.0f;
#pragma unroll
    for (int i = 0; i < 8; i++) {
        int off = i * 128 + lane * 4;
        float4 a = *(const float4*)(aff + off);
        float4 cc = *(const float4*)(c + off);
        float p0 = __expf(a.x - cc.x - r), p1 = __expf(a.y - cc.y - r);
        float p2 = __expf(a.z - cc.z - r), p3 = __expf(a.w - cc.w - r);
        p[4 * i] = p0; p[4 * i + 1] = p1; p[4 * i + 2] = p2; p[4 * i + 3] = p3;
        sum += p0 + p1 + p2 + p3;
    }
#pragma unroll
    for (int o = 16; o > 0; o >>= 1) sum += __shfl_xor_sync(0xffffffffu, sum, o);

    const float inv = 1.0f / (sum + 1e-8f);
    const float* t0 = tgt + (size_t)bb * 3 * MMM;
    float w0 = 0.0f, w1 = 0.0f, w2 = 0.0f;
    float* outrow = out_pn + (size_t)gw * MMM;
#pragma unroll
    for (int i = 0; i < 8; i++) {
        int off = i * 128 + lane * 4;
        float4 q;
        q.x = p[4 * i] * inv; q.y = p[4 * i + 1] * inv;
        q.z = p[4 * i + 2] * inv; q.w = p[4 * i + 3] * inv;
        __stcs((float4*)(outrow + off), q);   // streaming store
        float4 ta = *(const float4*)(t0 + off);
        float4 tb = *(const float4*)(t0 + MMM + off);
        float4 tc = *(const float4*)(t0 + 2 * MMM + off);
        w0 += q.x * ta.x + q.y * ta.y + q.z * ta.z + q.w * ta.w;
        w1 += q.x * tb.x + q.y * tb.y + q.z * tb.z + q.w * tb.w;
        w2 += q.x * tc.x + q.y * tc.y + q.z * tc.z + q.w * tc.w;
    }
#pragma unroll
    for (int o = 16; o > 0; o >>= 1) {
        w0 += __shfl_xor_sync(0xffffffffu, w0, o);
        w1 += __shfl_xor_sync(0xffffffffu, w1, o);
        w2 += __shfl_xor_sync(0xffffffffu, w2, o);
    }
    if (lane == 0) {
        g_weights[gw] = sum;
        g_wt[(size_t)bb * 3 * NN + n]          = w0;
        g_wt[(size_t)bb * 3 * NN + NN + n]     = w1;
        g_wt[(size_t)bb * 3 * NN + 2 * NN + n] = w2;
    }
}

// ---------------- per-batch Procrustes (double precision 3x3 SVD) ----------------
__device__ double block_reduce_d(double v, double* sred, int tid) {
    sred[tid] = v; __syncthreads();
    for (int s = 128; s > 0; s >>= 1) {
        if (tid < s) sred[tid] += sred[tid + s];
        __syncthreads();
    }
    double r = sred[0]; __syncthreads();
    return r;
}

__global__ __launch_bounds__(256) void procrustes_kernel(const float* __restrict__ src,
                                                         float* __restrict__ out) {
    const int bb = blockIdx.x, tid = threadIdx.x;
    __shared__ double sred[256];
    __shared__ double bc[16];

    const float* w  = g_weights + bb * NN;
    const float* wt = g_wt + (size_t)bb * 3 * NN;
    const float* sp = src + (size_t)bb * 3 * NN;

    double lv = 0.0;
    for (int n = tid; n < NN; n += 256) lv += (double)w[n];
    double wsum = block_reduce_d(lv, sred, tid);
    double denom = wsum + 1e-8;

    double acc[6] = {0, 0, 0, 0, 0, 0};
    for (int n = tid; n < NN; n += 256) {
        double wn = (double)w[n] / denom;
        acc[0] += (double)sp[n] * wn;
        acc[1] += (double)sp[NN + n] * wn;
        acc[2] += (double)sp[2 * NN + n] * wn;
        acc[3] += (double)wt[n] * wn;
        acc[4] += (double)wt[NN + n] * wn;
        acc[5] += (double)wt[2 * NN + n] * wn;
    }
    for (int q = 0; q < 6; q++) {
        double r = block_reduce_d(acc[q], sred, tid);
        if (tid == 0) bc[q] = r;
    }
    __syncthreads();
    double scent[3] = {bc[0], bc[1], bc[2]};
    double tcent[3] = {bc[3], bc[4], bc[5]};

    double h[9] = {0, 0, 0, 0, 0, 0, 0, 0, 0};
    for (int n = tid; n < NN; n += 256) {
        double wn = (double)w[n] / denom;
        double si[3] = {(double)sp[n] - scent[0],
                        (double)sp[NN + n] - scent[1],
                        (double)sp[2 * NN + n] - scent[2]};
        double tj[3] = {((double)wt[n] - tcent[0]) * wn,
                        ((double)wt[NN + n] - tcent[1]) * wn,
                        ((double)wt[2 * NN + n] - tcent[2]) * wn};
#pragma unroll
        for (int i = 0; i < 3; i++)
#pragma unroll
            for (int j = 0; j < 3; j++) h[i * 3 + j] += si[i] * tj[j];
    }
    for (int q = 0; q < 9; q++) {
        double r = block_reduce_d(h[q], sred, tid);
        if (tid == 0) bc[q] = r;
    }
    __syncthreads();

    if (tid == 0) {
        double H[3][3];
        for (int i = 0; i < 3; i++)
            for (int j = 0; j < 3; j++) H[i][j] = bc[i * 3 + j];
        double A[3][3];
        for (int i = 0; i < 3; i++)
            for (int j = 0; j < 3; j++)
                A[i][j] = H[0][i] * H[0][j] + H[1][i] * H[1][j] + H[2][i] * H[2][j];
        double V[3][3] = {{1, 0, 0}, {0, 1, 0}, {0, 0, 1}};
        for (int sweep = 0; sweep < 45; sweep++) {
            int r3 = sweep % 3;
            int p = (r3 == 2) ? 1 : 0;
            int q = (r3 == 0) ? 1 : 2;
            double apq = A[p][q];
            if (fabs(apq) < 1e-280) continue;
            double theta = (A[q][q] - A[p][p]) / (2.0 * apq);
            double tt = copysign(1.0, theta) / (fabs(theta) + sqrt(theta * theta + 1.0));
            double cc = 1.0 / sqrt(tt * tt + 1.0);
            double ssn = tt * cc;
            for (int k = 0; k < 3; k++) {
                double akp = A[k][p], akq = A[k][q];
                A[k][p] = cc * akp - ssn * akq;
                A[k][q] = ssn * akp + cc * akq;
            }
            for (int k = 0; k < 3; k++) {
                double apk = A[p][k], aqk = A[q][k];
                A[p][k] = cc * apk - ssn * aqk;
                A[q][k] = ssn * apk + cc * aqk;
            }
            for (int k = 0; k < 3; k++) {
                double vkp = V[k][p], vkq = V[k][q];
                V[k][p] = cc * vkp - ssn * vkq;
                V[k][q] = ssn * vkp + cc * vkq;
            }
        }
        double ev[3] = {A[0][0], A[1][1], A[2][2]};
        int idx[3] = {0, 1, 2};
        if (ev[idx[0]] < ev[idx[1]]) { int t2 = idx[0]; idx[0] = idx[1]; idx[1] = t2; }
        if (ev[idx[0]] < ev[idx[2]]) { int t2 = idx[0]; idx[0] = idx[2]; idx[2] = t2; }
        if (ev[idx[1]] < ev[idx[2]]) { int t2 = idx[1]; idx[1] = idx[2]; idx[2] = t2; }

        double Vs[3][3], U[3][3];
        for (int k = 0; k < 3; k++) {
            int c = idx[k];
            double sv = sqrt(fmax(ev[c], 0.0));
            double invs = (sv > 1e-30) ? 1.0 / sv : 0.0;
            for (int i = 0; i < 3; i++) Vs[i][k] = V[i][c];
            for (int i = 0; i < 3; i++)
                U[i][k] = (H[i][0] * V[0][c] + H[i][1] * V[1][c] + H[i][2] * V[2][c]) * invs;
        }
        double detH = H[0][0] * (H[1][1] * H[2][2] - H[1][2] * H[2][1])
                    - H[0][1] * (H[1][0] * H[2][2] - H[1][2] * H[2][0])
                    + H[0][2] * (H[1][0] * H[2][1] - H[1][1] * H[2][0]);
        double dsg = (detH >= 0.0) ? 1.0 : -1.0;
        double R[3][3];
        for (int i = 0; i < 3; i++)
            for (int j = 0; j < 3; j++)
                R[i][j] = Vs[i][0] * U[j][0] + Vs[i][1] * U[j][1] + dsg * Vs[i][2] * U[j][2];
        double tv[3];
        for (int i = 0; i < 3; i++)
            tv[i] = -(R[i][0] * scent[0] + R[i][1] * scent[1] + R[i][2] * scent[2]) + tcent[i];

        for (int i = 0; i < 3; i++)
            for (int j = 0; j < 3; j++)
                out[bb * 9 + i * 3 + j] = (float)R[i][j];
        for (int i = 0; i < 3; i++)
            out[BB * 9 + bb * 3 + i] = (float)tv[i];
    }
}

// ---------------- launch ----------------
extern "C" void kernel_launch(void* const* d_in, const int* in_sizes, int n_in,
                              void* d_out, int out_size) {
    const float* src_emb = (const float*)d_in[0];
    const float* tgt_emb = (const float*)d_in[1];
    const float* src     = (const float*)d_in[2];
    const float* tgt     = (const float*)d_in[3];
    const float* temp    = (const float*)d_in[4];
    float* out = (float*)d_out;
    float* out_pn = out + BB * 9 + BB * 3;

    init_kernel<<<64, 256>>>();                                             // launch 0
    convert_kernel<<<dim3(NN / 32, DKK / 32, 2 * BB), dim3(32, 8)>>>(src_emb, tgt_emb); // 1
    dummy_kernel<<<1, 32>>>();                                              // 2
    dummy_kernel<<<1, 32>>>();                                              // 3
    dummy_kernel<<<1, 32>>>();                                              // 4

    const int gemm_smem = 2 * STG_B;   // 128 KB
    cudaFuncSetAttribute(gemm_mma, cudaFuncAttributeMaxDynamicSharedMemorySize, gemm_smem);
    gemm_mma<<<dim3(MMM / 128, NN / 128, BB), 512, gemm_smem>>>(temp);      // launch 5 -> ncu

    for (int it = 0; it < 5; it++) {
        row_kernel<<<(BB * NN) / 8, 256>>>();
        colreduce_kernel<<<(BB * MMM) / 256, 256>>>();
    }
    final_kernel<<<(BB * NN) / 8, 256>>>(tgt, out_pn);
    procrustes_kernel<<<BB, 256>>>(src, out);
}

// round 7
// speedup vs baseline: 1.7640x; 1.0056x over previous
#include <cuda_runtime.h>
#include <cuda_bf16.h>
#include <math.h>
#include <stdint.h>

#define BB 16
#define DKK 512
#define NN 1024
#define MMM 1024

// ---------------- scratch (device globals) ----------------
__device__ float g_scores[(size_t)BB * NN * MMM];          // affinity, 64 MB (written once by GEMM)
__device__ __nv_bfloat16 g_shi[(size_t)BB * NN * DKK];     // src hi, transposed [b][n][d]
__device__ __nv_bfloat16 g_slo[(size_t)BB * NN * DKK];
__device__ __nv_bfloat16 g_thi[(size_t)BB * MMM * DKK];    // tgt hi, transposed [b][m][d]
__device__ __nv_bfloat16 g_tlo[(size_t)BB * MMM * DKK];
__device__ float g_cp[(size_t)BB * 128 * MMM];             // column partial sums, 8 MB
__device__ float g_r[BB * NN];                             // row duals (cumulative)
__device__ float g_c[BB * MMM];                            // col duals (cumulative)
__device__ float g_weights[BB * NN];
__device__ float g_wt[BB * 3 * NN];

// ---------------- PTX helpers (sm_80-class only) ----------------
__device__ __forceinline__ uint32_t smem_u32(const void* p) {
    uint32_t a;
    asm("{ .reg .u64 t; cvta.to.shared.u64 t, %1; cvt.u32.u64 %0, t; }" : "=r"(a) : "l"(p));
    return a;
}
#define LDSM4(r0, r1, r2, r3, addr) \
    asm volatile("ldmatrix.sync.aligned.m8n8.x4.shared.b16 {%0,%1,%2,%3}, [%4];" \
        : "=r"(r0), "=r"(r1), "=r"(r2), "=r"(r3) : "r"(addr))
#define MMA16816(c, a, b0, b1) \
    asm volatile("mma.sync.aligned.m16n8k16.row.col.f32.bf16.bf16.f32 " \
        "{%0,%1,%2,%3}, {%4,%5,%6,%7}, {%8,%9}, {%0,%1,%2,%3};" \
        : "+f"((c)[0]), "+f"((c)[1]), "+f"((c)[2]), "+f"((c)[3]) \
        : "r"((a)[0]), "r"((a)[1]), "r"((a)[2]), "r"((a)[3]), "r"(b0), "r"(b1))
#define CPASYNC16(saddr, gptr) \
    asm volatile("cp.async.cg.shared.global [%0], [%1], 16;" :: "r"(saddr), "l"(gptr))
#define CP_COMMIT() asm volatile("cp.async.commit_group;" ::: "memory")
#define CP_WAIT1()  asm volatile("cp.async.wait_group 1;" ::: "memory")
#define CP_WAIT0()  asm volatile("cp.async.wait_group 0;" ::: "memory")

__device__ __forceinline__ uint32_t sw128(uint32_t off) {
    return off ^ ((off >> 3) & 0x70);
}
__device__ __forceinline__ void stg_evl8(float* p, float4 v0, float4 v1) {
    asm volatile("st.global.L2::evict_last.v8.b32 [%0], {%1,%2,%3,%4,%5,%6,%7,%8};"
                 :: "l"(p),
                    "r"(__float_as_uint(v0.x)), "r"(__float_as_uint(v0.y)),
                    "r"(__float_as_uint(v0.z)), "r"(__float_as_uint(v0.w)),
                    "r"(__float_as_uint(v1.x)), "r"(__float_as_uint(v1.y)),
                    "r"(__float_as_uint(v1.z)), "r"(__float_as_uint(v1.w)) : "memory");
}

// ---------------- init: zero column duals ----------------
__global__ void init_kernel() {
    int i = blockIdx.x * blockDim.x + threadIdx.x;
    if (i < BB * MMM) g_c[i] = 0.0f;
}

// spacer: harness emits 2 launches before ours; profiled slot = our 4th launch -> gemm
__global__ void dummy_kernel() {
    if (threadIdx.x == 0) g_cp[0] = 0.0f;   // overwritten by row_kernel later
}

// ---------------- transpose + hi/lo bf16 split (vectorized bf16x2 stores) ----------------
__global__ __launch_bounds__(256) void convert_kernel(const float* __restrict__ srcE,
                                                      const float* __restrict__ tgtE) {
    __shared__ float s[32][33];
    const int z = blockIdx.z;
    const int bb = z & 15;
    const float* in = (z < 16) ? srcE : tgtE;
    __nv_bfloat16* hi = (z < 16) ? g_shi : g_thi;
    __nv_bfloat16* lo = (z < 16) ? g_slo : g_tlo;
    const int tid = threadIdx.x;
    const int tx = tid & 31, ty = tid >> 5;   // load phase: (32, 8)
    const int n = blockIdx.x * 32 + tx;
    const int d0 = blockIdx.y * 32;
#pragma unroll
    for (int j = 0; j < 4; j++)
        s[ty + 8 * j][tx] = in[((size_t)bb * DKK + d0 + ty + 8 * j) * NN + n];
    __syncthreads();
    // store phase: 512 bf16x2 pairs; p = tid, tid+256; n_local = p>>4, d = 2*(p&15)
#pragma unroll
    for (int q = 0; q < 2; q++) {
        int p = tid + q * 256;
        int nl = p >> 4;
        int d = (p & 15) * 2;
        int nn = blockIdx.x * 32 + nl;
        float v0 = s[d][nl], v1 = s[d + 1][nl];
        __nv_bfloat16 h0 = __float2bfloat16(v0), h1 = __float2bfloat16(v1);
        float r0 = v0 - __bfloat162float(h0), r1 = v1 - __bfloat162float(h1);
        size_t o = ((size_t)bb * NN + nn) * DKK + d0 + d;
        *(__nv_bfloat162*)(hi + o) = __nv_bfloat162(h0, h1);
        *(__nv_bfloat162*)(lo + o) = __nv_bfloat162(__float2bfloat16(r0), __float2bfloat16(r1));
    }
}

// ---------------- bf16-split GEMM via mma.sync ----------------
// 512 threads, 16 warps of 32x32; CTA tile 128x128; K chunks of 64; 3-stage pipeline.
// smem stage: 4 mats (Ah,Al,Bh,Bl) x 128 rows x 128B, SW128 swizzled. 64KB/stage x3.
#define MAT_B 16384
#define STG_B 65536

__global__ __launch_bounds__(512, 1) void gemm_mma(const float* __restrict__ temp) {
    extern __shared__ char sm_[];
    const uint32_t sb = smem_u32(sm_);
    const int tid = threadIdx.x, wid = tid >> 5, lane = tid & 31;
    const int mt = blockIdx.x, nt = blockIdx.y, bb = blockIdx.z;
    const int warp_m = wid & 3;     // 4 warps over 128 rows (32 each)
    const int warp_n = wid >> 2;    // 4 warps over 128 cols (32 each)

    const __nv_bfloat16* Ah = g_shi + ((size_t)bb * NN + nt * 128) * DKK;
    const __nv_bfloat16* Al = g_slo + ((size_t)bb * NN + nt * 128) * DKK;
    const __nv_bfloat16* Bh = g_thi + ((size_t)bb * MMM + mt * 128) * DKK;
    const __nv_bfloat16* Bl = g_tlo + ((size_t)bb * MMM + mt * 128) * DKK;

    // 4096 16B chunks per stage, 8 per thread
    auto stage_load = [&](int kc, int s) {
#pragma unroll
        for (int i = 0; i < 8; i++) {
            int q = tid + i * 512;
            int mat = q >> 10;          // 0..3: Ahi,Alo,Bhi,Blo
            int w = q & 1023;
            int row = w >> 3, c = w & 7;
            const __nv_bfloat16* base =
                (mat < 2) ? ((mat == 0) ? Ah : Al) : ((mat == 2) ? Bh : Bl);
            uint32_t saddr = sb + s * STG_B + mat * MAT_B + sw128(row * 128 + c * 16);
            const char* g = (const char*)(base + (size_t)row * DKK + kc * 64 + c * 8);
            CPASYNC16(saddr, g);
        }
        CP_COMMIT();
    };

    float acc[2][4][4];
#pragma unroll
    for (int i = 0; i < 2; i++)
#pragma unroll
        for (int j = 0; j < 4; j++)
#pragma unroll
            for (int k = 0; k < 4; k++) acc[i][j][k] = 0.0f;

    stage_load(0, 0);
    stage_load(1, 1);

    for (int kc = 0; kc < 8; kc++) {
        const int s = kc % 3;
        if (kc + 1 < 8) { CP_WAIT1(); }   // stage kc arrived (kc+1 may be in flight)
        else            { CP_WAIT0(); }
        __syncthreads();                  // single barrier per chunk
        if (kc + 2 < 8) stage_load(kc + 2, (kc + 2) % 3);

        const uint32_t stg = sb + (uint32_t)s * STG_B;

#pragma unroll
        for (int h = 0; h < 4; h++) {       // four k16 steps per 64-chunk
            uint32_t ah[2][4], al[2][4], bh[2][4], bl[2][4];
#pragma unroll
            for (int mf = 0; mf < 2; mf++) {
                uint32_t off = (uint32_t)((warp_m * 32 + mf * 16 + (lane & 15)) * 128
                              + h * 32 + (lane >> 4) * 16);
                uint32_t ad = stg + sw128(off);
                LDSM4(ah[mf][0], ah[mf][1], ah[mf][2], ah[mf][3], ad);
                LDSM4(al[mf][0], al[mf][1], al[mf][2], al[mf][3], ad + MAT_B);
            }
#pragma unroll
            for (int np = 0; np < 2; np++) {
                uint32_t off = (uint32_t)((warp_n * 32 + np * 16 + ((lane >> 4) & 1) * 8 + (lane & 7)) * 128
                              + h * 32 + ((lane >> 3) & 1) * 16);
                uint32_t bd = stg + 2 * MAT_B + sw128(off);
                LDSM4(bh[np][0], bh[np][1], bh[np][2], bh[np][3], bd);
                LDSM4(bl[np][0], bl[np][1], bl[np][2], bl[np][3], bd + MAT_B);
            }
            // hi*hi
#pragma unroll
            for (int mf = 0; mf < 2; mf++)
#pragma unroll
                for (int n8 = 0; n8 < 4; n8++) {
                    const int np = n8 >> 1, hf = (n8 & 1) * 2;
                    MMA16816(acc[mf][n8], ah[mf], bh[np][hf], bh[np][hf + 1]);
                }
            // hi*lo
#pragma unroll
            for (int mf = 0; mf < 2; mf++)
#pragma unroll
                for (int n8 = 0; n8 < 4; n8++) {
                    const int np = n8 >> 1, hf = (n8 & 1) * 2;
                    MMA16816(acc[mf][n8], ah[mf], bl[np][hf], bl[np][hf + 1]);
                }
            // lo*hi
#pragma unroll
            for (int mf = 0; mf < 2; mf++)
#pragma unroll
                for (int n8 = 0; n8 < 4; n8++) {
                    const int np = n8 >> 1, hf = (n8 & 1) * 2;
                    MMA16816(acc[mf][n8], al[mf], bh[np][hf], bh[np][hf + 1]);
                }
        }
    }
    __syncthreads();   // epilogue reuses stage smem

    // ---- epilogue: stage through smem (132-float padded rows), 32B coalesced stores ----
    float* smF = (float*)sm_;
#pragma unroll
    for (int mf = 0; mf < 2; mf++)
#pragma unroll
        for (int n8 = 0; n8 < 4; n8++) {
            int r0 = warp_m * 32 + mf * 16 + (lane >> 2);
            int col = warp_n * 32 + n8 * 8 + (lane & 3) * 2;
            *(float2*)(smF + r0 * 132 + col)       = make_float2(acc[mf][n8][0], acc[mf][n8][1]);
            *(float2*)(smF + (r0 + 8) * 132 + col) = make_float2(acc[mf][n8][2], acc[mf][n8][3]);
        }
    __syncthreads();

    const float alpha = rsqrtf((float)DKK) / temp[bb];
    float* C = g_scores + (size_t)bb * NN * MMM + (size_t)(nt * 128) * MMM + mt * 128;
#pragma unroll
    for (int i = 0; i < 4; i++) {
        int idx = tid + i * 512;            // 0..2047 chunks of 8 floats
        int row = idx >> 4, c8 = idx & 15;
        const float* sp = smF + row * 132 + c8 * 8;
        float4 v0 = *(const float4*)sp;
        float4 v1 = *(const float4*)(sp + 4);
        v0.x *= alpha; v0.y *= alpha; v0.z *= alpha; v0.w *= alpha;
        v1.x *= alpha; v1.y *= alpha; v1.z *= alpha; v1.w *= alpha;
        stg_evl8(C + (size_t)row * MMM + c8 * 8, v0, v1);
    }
}

// ---------------- row pass: r[n] = LSE_m(aff - c, 0); emit column exp-partials ----------------
// x held in registers; single scaled-exp write to smem, then block reduce.
__global__ __launch_bounds__(256) void row_kernel() {
    __shared__ float s_p[8][1024];
    const int w    = threadIdx.x >> 5;
    const int lane = threadIdx.x & 31;
    const int gw   = blockIdx.x * 8 + w;
    const int bb   = gw >> 10;
    const float* aff = g_scores + (size_t)gw * MMM;
    const float* c   = g_c + bb * MMM;

    float x[32];
    float mx = 0.0f;    // slack term 0 included
#pragma unroll
    for (int i = 0; i < 8; i++) {
        int off = i * 128 + lane * 4;
        float4 a = *(const float4*)(aff + off);
        float4 cc = *(const float4*)(c + off);
        x[4 * i]     = a.x - cc.x;
        x[4 * i + 1] = a.y - cc.y;
        x[4 * i + 2] = a.z - cc.z;
        x[4 * i + 3] = a.w - cc.w;
        mx = fmaxf(mx, fmaxf(fmaxf(x[4 * i], x[4 * i + 1]), fmaxf(x[4 * i + 2], x[4 * i + 3])));
    }
#pragma unroll
    for (int o = 16; o > 0; o >>= 1) mx = fmaxf(mx, __shfl_xor_sync(0xffffffffu, mx, o));

    float s = 0.0f;
#pragma unroll
    for (int i = 0; i < 32; i++) { x[i] = __expf(x[i] - mx); s += x[i]; }
#pragma unroll
    for (int o = 16; o > 0; o >>= 1) s += __shfl_xor_sync(0xffffffffu, s, o);
    s += __expf(-mx);                    // slack

    const float r = mx + logf(s);
    if (lane == 0) g_r[gw] = r;
    const float scale = __expf(mx - r);  // = 1/s

#pragma unroll
    for (int i = 0; i < 8; i++) {
        int off = i * 128 + lane * 4;
        float4 e;
        e.x = x[4 * i] * scale;     e.y = x[4 * i + 1] * scale;
        e.z = x[4 * i + 2] * scale; e.w = x[4 * i + 3] * scale;
        *(float4*)(&s_p[w][off]) = e;
    }
    __syncthreads();

    const int t = threadIdx.x;
    float4 acc = *(const float4*)(&s_p[0][t * 4]);
#pragma unroll
    for (int ww = 1; ww < 8; ww++) {
        float4 v = *(const float4*)(&s_p[ww][t * 4]);
        acc.x += v.x; acc.y += v.y; acc.z += v.z; acc.w += v.w;
    }
    const int rb = blockIdx.x & 127;
    *(float4*)(g_cp + ((size_t)(bb * 128 + rb)) * 1024 + t * 4) = acc;
}

// ---------------- column reduce: c = c_old + log(S + exp(-c_old)) ----------------
__global__ __launch_bounds__(256) void colreduce_kernel() {
    const int idx = blockIdx.x * 256 + threadIdx.x;   // < 16384
    const int b = idx >> 10, m = idx & 1023;
    const float* cp = g_cp + (size_t)b * 128 * 1024 + m;
    float S = 0.0f;
#pragma unroll 8
    for (int rb = 0; rb < 128; rb++) S += cp[(size_t)rb * 1024];
    const float co = g_c[idx];
    g_c[idx] = co + logf(S + __expf(-co));
}

// ---------------- final: perm_norm, weights, weighted_tgt ----------------
__global__ __launch_bounds__(256) void final_kernel(const float* __restrict__ tgt,
                                                    float* __restrict__ out_pn) {
    const int gw   = (blockIdx.x * 256 + threadIdx.x) >> 5;
    const int lane = threadIdx.x & 31;
    const int bb   = gw >> 10;
    const int n    = gw & 1023;
    const float* aff = g_scores + (size_t)gw * MMM;
    const float* c   = g_c + bb * MMM;
    const float r    = g_r[gw];

    float p[32];
    float sum = 0.0f;
#pragma unroll
    for (int i = 0; i < 8; i++) {
        int off = i * 128 + lane * 4;
        float4 a = *(const float4*)(aff + off);
        float4 cc = *(const float4*)(c + off);
        float p0 = __expf(a.x - cc.x - r), p1 = __expf(a.y - cc.y - r);
        float p2 = __expf(a.z - cc.z - r), p3 = __expf(a.w - cc.w - r);
        p[4 * i] = p0; p[4 * i + 1] = p1; p[4 * i + 2] = p2; p[4 * i + 3] = p3;
        sum += p0 + p1 + p2 + p3;
    }
#pragma unroll
    for (int o = 16; o > 0; o >>= 1) sum += __shfl_xor_sync(0xffffffffu, sum, o);

    const float inv = 1.0f / (sum + 1e-8f);
    const float* t0 = tgt + (size_t)bb * 3 * MMM;
    float w0 = 0.0f, w1 = 0.0f, w2 = 0.0f;
    float* outrow = out_pn + (size_t)gw * MMM;
#pragma unroll
    for (int i = 0; i < 8; i++) {
        int off = i * 128 + lane * 4;
        float4 q;
        q.x = p[4 * i] * inv; q.y = p[4 * i + 1] * inv;
        q.z = p[4 * i + 2] * inv; q.w = p[4 * i + 3] * inv;
        __stcs((float4*)(outrow + off), q);   // streaming store
        float4 ta = *(const float4*)(t0 + off);
        float4 tb = *(const float4*)(t0 + MMM + off);
        float4 tc = *(const float4*)(t0 + 2 * MMM + off);
        w0 += q.x * ta.x + q.y * ta.y + q.z * ta.z + q.w * ta.w;
        w1 += q.x * tb.x + q.y * tb.y + q.z * tb.z + q.w * tb.w;
        w2 += q.x * tc.x + q.y * tc.y + q.z * tc.z + q.w * tc.w;
    }
#pragma unroll
    for (int o = 16; o > 0; o >>= 1) {
        w0 += __shfl_xor_sync(0xffffffffu, w0, o);
        w1 += __shfl_xor_sync(0xffffffffu, w1, o);
        w2 += __shfl_xor_sync(0xffffffffu, w2, o);
    }
    if (lane == 0) {
        g_weights[gw] = sum;
        g_wt[(size_t)bb * 3 * NN + n]          = w0;
        g_wt[(size_t)bb * 3 * NN + NN + n]     = w1;
        g_wt[(size_t)bb * 3 * NN + 2 * NN + n] = w2;
    }
}

// ---------------- per-batch Procrustes (double precision 3x3 SVD) ----------------
__device__ double block_reduce_d(double v, double* sred, int tid) {
    sred[tid] = v; __syncthreads();
    for (int s = 128; s > 0; s >>= 1) {
        if (tid < s) sred[tid] += sred[tid + s];
        __syncthreads();
    }
    double r = sred[0]; __syncthreads();
    return r;
}

__global__ __launch_bounds__(256) void procrustes_kernel(const float* __restrict__ src,
                                                         float* __restrict__ out) {
    const int bb = blockIdx.x, tid = threadIdx.x;
    __shared__ double sred[256];
    __shared__ double bc[16];

    const float* w  = g_weights + bb * NN;
    const float* wt = g_wt + (size_t)bb * 3 * NN;
    const float* sp = src + (size_t)bb * 3 * NN;

    double lv = 0.0;
    for (int n = tid; n < NN; n += 256) lv += (double)w[n];
    double wsum = block_reduce_d(lv, sred, tid);
    double denom = wsum + 1e-8;

    double acc[6] = {0, 0, 0, 0, 0, 0};
    for (int n = tid; n < NN; n += 256) {
        double wn = (double)w[n] / denom;
        acc[0] += (double)sp[n] * wn;
        acc[1] += (double)sp[NN + n] * wn;
        acc[2] += (double)sp[2 * NN + n] * wn;
        acc[3] += (double)wt[n] * wn;
        acc[4] += (double)wt[NN + n] * wn;
        acc[5] += (double)wt[2 * NN + n] * wn;
    }
    for (int q = 0; q < 6; q++) {
        double r = block_reduce_d(acc[q], sred, tid);
        if (tid == 0) bc[q] = r;
    }
    __syncthreads();
    double scent[3] = {bc[0], bc[1], bc[2]};
    double tcent[3] = {bc[3], bc[4], bc[5]};

    double h[9] = {0, 0, 0, 0, 0, 0, 0, 0, 0};
    for (int n = tid; n < NN; n += 256) {
        double wn = (double)w[n] / denom;
        double si[3] = {(double)sp[n] - scent[0],
                        (double)sp[NN + n] - scent[1],
                        (double)sp[2 * NN + n] - scent[2]};
        double tj[3] = {((double)wt[n] - tcent[0]) * wn,
                        ((double)wt[NN + n] - tcent[1]) * wn,
                        ((double)wt[2 * NN + n] - tcent[2]) * wn};
#pragma unroll
        for (int i = 0; i < 3; i++)
#pragma unroll
            for (int j = 0; j < 3; j++) h[i * 3 + j] += si[i] * tj[j];
    }
    for (int q = 0; q < 9; q++) {
        double r = block_reduce_d(h[q], sred, tid);
        if (tid == 0) bc[q] = r;
    }
    __syncthreads();

    if (tid == 0) {
        double H[3][3];
        for (int i = 0; i < 3; i++)
            for (int j = 0; j < 3; j++) H[i][j] = bc[i * 3 + j];
        double A[3][3];
        for (int i = 0; i < 3; i++)
            for (int j = 0; j < 3; j++)
                A[i][j] = H[0][i] * H[0][j] + H[1][i] * H[1][j] + H[2][i] * H[2][j];
        double V[3][3] = {{1, 0, 0}, {0, 1, 0}, {0, 0, 1}};
        for (int sweep = 0; sweep < 45; sweep++) {
            int r3 = sweep % 3;
            int p = (r3 == 2) ? 1 : 0;
            int q = (r3 == 0) ? 1 : 2;
            double apq = A[p][q];
            if (fabs(apq) < 1e-280) continue;
            double theta = (A[q][q] - A[p][p]) / (2.0 * apq);
            double tt = copysign(1.0, theta) / (fabs(theta) + sqrt(theta * theta + 1.0));
            double cc = 1.0 / sqrt(tt * tt + 1.0);
            double ssn = tt * cc;
            for (int k = 0; k < 3; k++) {
                double akp = A[k][p], akq = A[k][q];
                A[k][p] = cc * akp - ssn * akq;
                A[k][q] = ssn * akp + cc * akq;
            }
            for (int k = 0; k < 3; k++) {
                double apk = A[p][k], aqk = A[q][k];
                A[p][k] = cc * apk - ssn * aqk;
                A[q][k] = ssn * apk + cc * aqk;
            }
            for (int k = 0; k < 3; k++) {
                double vkp = V[k][p], vkq = V[k][q];
                V[k][p] = cc * vkp - ssn * vkq;
                V[k][q] = ssn * vkp + cc * vkq;
            }
        }
        double ev[3] = {A[0][0], A[1][1], A[2][2]};
        int idx[3] = {0, 1, 2};
        if (ev[idx[0]] < ev[idx[1]]) { int t2 = idx[0]; idx[0] = idx[1]; idx[1] = t2; }
        if (ev[idx[0]] < ev[idx[2]]) { int t2 = idx[0]; idx[0] = idx[2]; idx[2] = t2; }
        if (ev[idx[1]] < ev[idx[2]]) { int t2 = idx[1]; idx[1] = idx[2]; idx[2] = t2; }

        double Vs[3][3], U[3][3];
        for (int k = 0; k < 3; k++) {
            int c = idx[k];
            double sv = sqrt(fmax(ev[c], 0.0));
            double invs = (sv > 1e-30) ? 1.0 / sv : 0.0;
            for (int i = 0; i < 3; i++) Vs[i][k] = V[i][c];
            for (int i = 0; i < 3; i++)
                U[i][k] = (H[i][0] * V[0][c] + H[i][1] * V[1][c] + H[i][2] * V[2][c]) * invs;
        }
        double detH = H[0][0] * (H[1][1] * H[2][2] - H[1][2] * H[2][1])
                    - H[0][1] * (H[1][0] * H[2][2] - H[1][2] * H[2][0])
                    + H[0][2] * (H[1][0] * H[2][1] - H[1][1] * H[2][0]);
        double dsg = (detH >= 0.0) ? 1.0 : -1.0;
        double R[3][3];
        for (int i = 0; i < 3; i++)
            for (int j = 0; j < 3; j++)
                R[i][j] = Vs[i][0] * U[j][0] + Vs[i][1] * U[j][1] + dsg * Vs[i][2] * U[j][2];
        double tv[3];
        for (int i = 0; i < 3; i++)
            tv[i] = -(R[i][0] * scent[0] + R[i][1] * scent[1] + R[i][2] * scent[2]) + tcent[i];

        for (int i = 0; i < 3; i++)
            for (int j = 0; j < 3; j++)
                out[bb * 9 + i * 3 + j] = (float)R[i][j];
        for (int i = 0; i < 3; i++)
            out[BB * 9 + bb * 3 + i] = (float)tv[i];
    }
}

// ---------------- launch ----------------
extern "C" void kernel_launch(void* const* d_in, const int* in_sizes, int n_in,
                              void* d_out, int out_size) {
    const float* src_emb = (const float*)d_in[0];
    const float* tgt_emb = (const float*)d_in[1];
    const float* src     = (const float*)d_in[2];
    const float* tgt     = (const float*)d_in[3];
    const float* temp    = (const float*)d_in[4];
    float* out = (float*)d_out;
    float* out_pn = out + BB * 9 + BB * 3;

    init_kernel<<<64, 256>>>();                                             // our launch 0
    convert_kernel<<<dim3(NN / 32, DKK / 32, 2 * BB), dim3(256)>>>(src_emb, tgt_emb); // 1
    dummy_kernel<<<1, 32>>>();                                              // 2

    const int gemm_smem = 3 * STG_B;   // 192 KB
    cudaFuncSetAttribute(gemm_mma, cudaFuncAttributeMaxDynamicSharedMemorySize, gemm_smem);
    gemm_mma<<<dim3(MMM / 128, NN / 128, BB), 512, gemm_smem>>>(temp);      // 3 -> profiled

    for (int it = 0; it < 5; it++) {
        row_kernel<<<(BB * NN) / 8, 256>>>();
        colreduce_kernel<<<(BB * MMM) / 256, 256>>>();
    }
    final_kernel<<<(BB * NN) / 8, 256>>>(tgt, out_pn);
    procrustes_kernel<<<BB, 256>>>(src, out);
}

// round 8
// speedup vs baseline: 2.4978x; 1.4160x over previous
#include <cuda_runtime.h>
#include <cuda_bf16.h>
#include <math.h>
#include <stdint.h>

#define BB 16
#define DKK 512
#define NN 1024
#define MMM 1024

// ---------------- scratch (device globals) ----------------
__device__ float g_scores[(size_t)BB * NN * MMM];          // affinity, 64 MB (written once by GEMM)
__device__ __nv_bfloat16 g_shi[(size_t)BB * NN * DKK];     // src hi, transposed [b][n][d]
__device__ __nv_bfloat16 g_slo[(size_t)BB * NN * DKK];
__device__ __nv_bfloat16 g_thi[(size_t)BB * MMM * DKK];    // tgt hi, transposed [b][m][d]
__device__ __nv_bfloat16 g_tlo[(size_t)BB * MMM * DKK];
__device__ float g_cp[(size_t)BB * 128 * MMM];             // column partial sums, 8 MB
__device__ float g_r[BB * NN];                             // row duals (cumulative)
__device__ float g_c[BB * MMM];                            // col duals (cumulative)
__device__ float g_weights[BB * NN];
__device__ float g_wt[BB * 3 * NN];

// ---------------- PTX helpers (sm_80-class only) ----------------
__device__ __forceinline__ uint32_t smem_u32(const void* p) {
    uint32_t a;
    asm("{ .reg .u64 t; cvta.to.shared.u64 t, %1; cvt.u32.u64 %0, t; }" : "=r"(a) : "l"(p));
    return a;
}
#define LDSM4(r0, r1, r2, r3, addr) \
    asm volatile("ldmatrix.sync.aligned.m8n8.x4.shared.b16 {%0,%1,%2,%3}, [%4];" \
        : "=r"(r0), "=r"(r1), "=r"(r2), "=r"(r3) : "r"(addr))
#define MMA16816(c, a, b0, b1) \
    asm volatile("mma.sync.aligned.m16n8k16.row.col.f32.bf16.bf16.f32 " \
        "{%0,%1,%2,%3}, {%4,%5,%6,%7}, {%8,%9}, {%0,%1,%2,%3};" \
        : "+f"((c)[0]), "+f"((c)[1]), "+f"((c)[2]), "+f"((c)[3]) \
        : "r"((a)[0]), "r"((a)[1]), "r"((a)[2]), "r"((a)[3]), "r"(b0), "r"(b1))
#define CPASYNC16(saddr, gptr) \
    asm volatile("cp.async.cg.shared.global [%0], [%1], 16;" :: "r"(saddr), "l"(gptr))
#define CP_COMMIT() asm volatile("cp.async.commit_group;" ::: "memory")
#define CP_WAIT1()  asm volatile("cp.async.wait_group 1;" ::: "memory")
#define CP_WAIT0()  asm volatile("cp.async.wait_group 0;" ::: "memory")

__device__ __forceinline__ uint32_t sw128(uint32_t off) {
    return off ^ ((off >> 3) & 0x70);
}
__device__ __forceinline__ void stg_evl8(float* p, float4 v0, float4 v1) {
    asm volatile("st.global.L2::evict_last.v8.b32 [%0], {%1,%2,%3,%4,%5,%6,%7,%8};"
                 :: "l"(p),
                    "r"(__float_as_uint(v0.x)), "r"(__float_as_uint(v0.y)),
                    "r"(__float_as_uint(v0.z)), "r"(__float_as_uint(v0.w)),
                    "r"(__float_as_uint(v1.x)), "r"(__float_as_uint(v1.y)),
                    "r"(__float_as_uint(v1.z)), "r"(__float_as_uint(v1.w)) : "memory");
}

// ---------------- init: zero column duals ----------------
__global__ void init_kernel() {
    int i = blockIdx.x * blockDim.x + threadIdx.x;
    if (i < BB * MMM) g_c[i] = 0.0f;
}

// ---------------- transpose + hi/lo bf16 split (vectorized bf16x2 stores) ----------------
__global__ __launch_bounds__(256) void convert_kernel(const float* __restrict__ srcE,
                                                      const float* __restrict__ tgtE) {
    __shared__ float s[32][33];
    const int z = blockIdx.z;
    const int bb = z & 15;
    const float* in = (z < 16) ? srcE : tgtE;
    __nv_bfloat16* hi = (z < 16) ? g_shi : g_thi;
    __nv_bfloat16* lo = (z < 16) ? g_slo : g_tlo;
    const int tid = threadIdx.x;
    const int tx = tid & 31, ty = tid >> 5;   // load phase: (32, 8)
    const int n = blockIdx.x * 32 + tx;
    const int d0 = blockIdx.y * 32;
#pragma unroll
    for (int j = 0; j < 4; j++)
        s[ty + 8 * j][tx] = in[((size_t)bb * DKK + d0 + ty + 8 * j) * NN + n];
    __syncthreads();
#pragma unroll
    for (int q = 0; q < 2; q++) {
        int p = tid + q * 256;
        int nl = p >> 4;
        int d = (p & 15) * 2;
        int nn = blockIdx.x * 32 + nl;
        float v0 = s[d][nl], v1 = s[d + 1][nl];
        __nv_bfloat16 h0 = __float2bfloat16(v0), h1 = __float2bfloat16(v1);
        float r0 = v0 - __bfloat162float(h0), r1 = v1 - __bfloat162float(h1);
        size_t o = ((size_t)bb * NN + nn) * DKK + d0 + d;
        *(__nv_bfloat162*)(hi + o) = __nv_bfloat162(h0, h1);
        *(__nv_bfloat162*)(lo + o) = __nv_bfloat162(__float2bfloat16(r0), __float2bfloat16(r1));
    }
}

// ---------------- bf16-split GEMM via mma.sync ----------------
#define MAT_B 16384
#define STG_B 65536

__global__ __launch_bounds__(512, 1) void gemm_mma(const float* __restrict__ temp) {
    extern __shared__ char sm_[];
    const uint32_t sb = smem_u32(sm_);
    const int tid = threadIdx.x, wid = tid >> 5, lane = tid & 31;
    const int mt = blockIdx.x, nt = blockIdx.y, bb = blockIdx.z;
    const int warp_m = wid & 3;
    const int warp_n = wid >> 2;

    const __nv_bfloat16* Ah = g_shi + ((size_t)bb * NN + nt * 128) * DKK;
    const __nv_bfloat16* Al = g_slo + ((size_t)bb * NN + nt * 128) * DKK;
    const __nv_bfloat16* Bh = g_thi + ((size_t)bb * MMM + mt * 128) * DKK;
    const __nv_bfloat16* Bl = g_tlo + ((size_t)bb * MMM + mt * 128) * DKK;

    auto stage_load = [&](int kc, int s) {
#pragma unroll
        for (int i = 0; i < 8; i++) {
            int q = tid + i * 512;
            int mat = q >> 10;
            int w = q & 1023;
            int row = w >> 3, c = w & 7;
            const __nv_bfloat16* base =
                (mat < 2) ? ((mat == 0) ? Ah : Al) : ((mat == 2) ? Bh : Bl);
            uint32_t saddr = sb + s * STG_B + mat * MAT_B + sw128(row * 128 + c * 16);
            const char* g = (const char*)(base + (size_t)row * DKK + kc * 64 + c * 8);
            CPASYNC16(saddr, g);
        }
        CP_COMMIT();
    };

    float acc[2][4][4];
#pragma unroll
    for (int i = 0; i < 2; i++)
#pragma unroll
        for (int j = 0; j < 4; j++)
#pragma unroll
            for (int k = 0; k < 4; k++) acc[i][j][k] = 0.0f;

    stage_load(0, 0);
    stage_load(1, 1);

    for (int kc = 0; kc < 8; kc++) {
        const int s = kc % 3;
        if (kc + 1 < 8) { CP_WAIT1(); }
        else            { CP_WAIT0(); }
        __syncthreads();
        if (kc + 2 < 8) stage_load(kc + 2, (kc + 2) % 3);

        const uint32_t stg = sb + (uint32_t)s * STG_B;

#pragma unroll
        for (int h = 0; h < 4; h++) {
            uint32_t ah[2][4], al[2][4], bh[2][4], bl[2][4];
#pragma unroll
            for (int mf = 0; mf < 2; mf++) {
                uint32_t off = (uint32_t)((warp_m * 32 + mf * 16 + (lane & 15)) * 128
                              + h * 32 + (lane >> 4) * 16);
                uint32_t ad = stg + sw128(off);
                LDSM4(ah[mf][0], ah[mf][1], ah[mf][2], ah[mf][3], ad);
                LDSM4(al[mf][0], al[mf][1], al[mf][2], al[mf][3], ad + MAT_B);
            }
#pragma unroll
            for (int np = 0; np < 2; np++) {
                uint32_t off = (uint32_t)((warp_n * 32 + np * 16 + ((lane >> 4) & 1) * 8 + (lane & 7)) * 128
                              + h * 32 + ((lane >> 3) & 1) * 16);
                uint32_t bd = stg + 2 * MAT_B + sw128(off);
                LDSM4(bh[np][0], bh[np][1], bh[np][2], bh[np][3], bd);
                LDSM4(bl[np][0], bl[np][1], bl[np][2], bl[np][3], bd + MAT_B);
            }
#pragma unroll
            for (int mf = 0; mf < 2; mf++)
#pragma unroll
                for (int n8 = 0; n8 < 4; n8++) {
                    const int np = n8 >> 1, hf = (n8 & 1) * 2;
                    MMA16816(acc[mf][n8], ah[mf], bh[np][hf], bh[np][hf + 1]);
                }
#pragma unroll
            for (int mf = 0; mf < 2; mf++)
#pragma unroll
                for (int n8 = 0; n8 < 4; n8++) {
                    const int np = n8 >> 1, hf = (n8 & 1) * 2;
                    MMA16816(acc[mf][n8], ah[mf], bl[np][hf], bl[np][hf + 1]);
                }
#pragma unroll
            for (int mf = 0; mf < 2; mf++)
#pragma unroll
                for (int n8 = 0; n8 < 4; n8++) {
                    const int np = n8 >> 1, hf = (n8 & 1) * 2;
                    MMA16816(acc[mf][n8], al[mf], bh[np][hf], bh[np][hf + 1]);
                }
        }
    }
    __syncthreads();

    float* smF = (float*)sm_;
#pragma unroll
    for (int mf = 0; mf < 2; mf++)
#pragma unroll
        for (int n8 = 0; n8 < 4; n8++) {
            int r0 = warp_m * 32 + mf * 16 + (lane >> 2);
            int col = warp_n * 32 + n8 * 8 + (lane & 3) * 2;
            *(float2*)(smF + r0 * 132 + col)       = make_float2(acc[mf][n8][0], acc[mf][n8][1]);
            *(float2*)(smF + (r0 + 8) * 132 + col) = make_float2(acc[mf][n8][2], acc[mf][n8][3]);
        }
    __syncthreads();

    const float alpha = rsqrtf((float)DKK) / temp[bb];
    float* C = g_scores + (size_t)bb * NN * MMM + (size_t)(nt * 128) * MMM + mt * 128;
#pragma unroll
    for (int i = 0; i < 4; i++) {
        int idx = tid + i * 512;
        int row = idx >> 4, c8 = idx & 15;
        const float* sp = smF + row * 132 + c8 * 8;
        float4 v0 = *(const float4*)sp;
        float4 v1 = *(const float4*)(sp + 4);
        v0.x *= alpha; v0.y *= alpha; v0.z *= alpha; v0.w *= alpha;
        v1.x *= alpha; v1.y *= alpha; v1.z *= alpha; v1.w *= alpha;
        stg_evl8(C + (size_t)row * MMM + c8 * 8, v0, v1);
    }
}

// ---------------- row pass: cp.async-staged; r[n] = LSE_m(aff - c, 0); emit col partials ----------------
__global__ __launch_bounds__(256) void row_kernel() {
    __shared__ float s_aff[8][1024];   // aff tile, reused in-place for scaled partials
    __shared__ float s_c[1024];        // per-batch column duals (shared by all 8 rows)
    const int tid  = threadIdx.x;
    const int w    = tid >> 5;
    const int lane = tid & 31;
    const int gw   = blockIdx.x * 8 + w;
    const int bb   = gw >> 10;
    const uint32_t sb_aff = smem_u32(&s_aff[0][0]);
    const uint32_t sb_c   = smem_u32(&s_c[0]);

    // stage c row (4KB): 1 chunk of 16B per thread
    CPASYNC16(sb_c + tid * 16, (const char*)(g_c + bb * MMM + tid * 4));
    // stage 8 aff rows (32KB): 8 chunks per thread
    const float* affbase = g_scores + (size_t)(blockIdx.x * 8) * MMM;
#pragma unroll
    for (int i = 0; i < 8; i++) {
        int q = tid + i * 256;          // 0..2047, row = q>>8, chunk = q&255
        CPASYNC16(sb_aff + q * 16, (const char*)(affbase + (size_t)(q >> 8) * MMM + (q & 255) * 4));
    }
    CP_COMMIT();
    CP_WAIT0();
    __syncthreads();

    float x[32];
    float mx = 0.0f;    // slack term 0 included
#pragma unroll
    for (int i = 0; i < 8; i++) {
        int off = i * 128 + lane * 4;
        float4 a = *(const float4*)(&s_aff[w][off]);
        float4 cc = *(const float4*)(&s_c[off]);
        x[4 * i]     = a.x - cc.x;
        x[4 * i + 1] = a.y - cc.y;
        x[4 * i + 2] = a.z - cc.z;
        x[4 * i + 3] = a.w - cc.w;
        mx = fmaxf(mx, fmaxf(fmaxf(x[4 * i], x[4 * i + 1]), fmaxf(x[4 * i + 2], x[4 * i + 3])));
    }
#pragma unroll
    for (int o = 16; o > 0; o >>= 1) mx = fmaxf(mx, __shfl_xor_sync(0xffffffffu, mx, o));

    float s = 0.0f;
#pragma unroll
    for (int i = 0; i < 32; i++) { x[i] = __expf(x[i] - mx); s += x[i]; }
#pragma unroll
    for (int o = 16; o > 0; o >>= 1) s += __shfl_xor_sync(0xffffffffu, s, o);
    s += __expf(-mx);                    // slack

    const float r = mx + logf(s);
    if (lane == 0) g_r[gw] = r;
    const float scale = __expf(mx - r);  // = 1/s

    __syncthreads();                     // all warps done reading x before overwrite
#pragma unroll
    for (int i = 0; i < 8; i++) {
        int off = i * 128 + lane * 4;
        float4 e;
        e.x = x[4 * i] * scale;     e.y = x[4 * i + 1] * scale;
        e.z = x[4 * i + 2] * scale; e.w = x[4 * i + 3] * scale;
        *(float4*)(&s_aff[w][off]) = e;
    }
    __syncthreads();

    float4 acc = *(const float4*)(&s_aff[0][tid * 4]);
#pragma unroll
    for (int ww = 1; ww < 8; ww++) {
        float4 v = *(const float4*)(&s_aff[ww][tid * 4]);
        acc.x += v.x; acc.y += v.y; acc.z += v.z; acc.w += v.w;
    }
    const int rb = blockIdx.x & 127;
    *(float4*)(g_cp + ((size_t)(bb * 128 + rb)) * 1024 + tid * 4) = acc;
}

// ---------------- column reduce: c = c_old + log(S + exp(-c_old)) ----------------
__global__ __launch_bounds__(256) void colreduce_kernel() {
    const int idx = blockIdx.x * 256 + threadIdx.x;   // < 16384
    const int b = idx >> 10, m = idx & 1023;
    const float* cp = g_cp + (size_t)b * 128 * 1024 + m;
    float S = 0.0f;
#pragma unroll 8
    for (int rb = 0; rb < 128; rb++) S += cp[(size_t)rb * 1024];
    const float co = g_c[idx];
    g_c[idx] = co + logf(S + __expf(-co));
}

// ---------------- final: perm_norm, weights, weighted_tgt ----------------
__global__ __launch_bounds__(256) void final_kernel(const float* __restrict__ tgt,
                                                    float* __restrict__ out_pn) {
    const int gw   = (blockIdx.x * 256 + threadIdx.x) >> 5;
    const int lane = threadIdx.x & 31;
    const int bb   = gw >> 10;
    const int n    = gw & 1023;
    const float* aff = g_scores + (size_t)gw * MMM;
    const float* c   = g_c + bb * MMM;
    const float r    = g_r[gw];

    float p[32];
    float sum = 0.0f;
#pragma unroll
    for (int i = 0; i < 8; i++) {
        int off = i * 128 + lane * 4;
        float4 a = *(const float4*)(aff + off);
        float4 cc = *(const float4*)(c + off);
        float p0 = __expf(a.x - cc.x - r), p1 = __expf(a.y - cc.y - r);
        float p2 = __expf(a.z - cc.z - r), p3 = __expf(a.w - cc.w - r);
        p[4 * i] = p0; p[4 * i + 1] = p1; p[4 * i + 2] = p2; p[4 * i + 3] = p3;
        sum += p0 + p1 + p2 + p3;
    }
#pragma unroll
    for (int o = 16; o > 0; o >>= 1) sum += __shfl_xor_sync(0xffffffffu, sum, o);

    const float inv = 1.0f / (sum + 1e-8f);
    const float* t0 = tgt + (size_t)bb * 3 * MMM;
    float w0 = 0.0f, w1 = 0.0f, w2 = 0.0f;
    float* outrow = out_pn + (size_t)gw * MMM;
#pragma unroll
    for (int i = 0; i < 8; i++) {
        int off = i * 128 + lane * 4;
        float4 q;
        q.x = p[4 * i] * inv; q.y = p[4 * i + 1] * inv;
        q.z = p[4 * i + 2] * inv; q.w = p[4 * i + 3] * inv;
        __stcs((float4*)(outrow + off), q);
        float4 ta = *(const float4*)(t0 + off);
        float4 tb = *(const float4*)(t0 + MMM + off);
        float4 tc = *(const float4*)(t0 + 2 * MMM + off);
        w0 += q.x * ta.x + q.y * ta.y + q.z * ta.z + q.w * ta.w;
        w1 += q.x * tb.x + q.y * tb.y + q.z * tb.z + q.w * tb.w;
        w2 += q.x * tc.x + q.y * tc.y + q.z * tc.z + q.w * tc.w;
    }
#pragma unroll
    for (int o = 16; o > 0; o >>= 1) {
        w0 += __shfl_xor_sync(0xffffffffu, w0, o);
        w1 += __shfl_xor_sync(0xffffffffu, w1, o);
        w2 += __shfl_xor_sync(0xffffffffu, w2, o);
    }
    if (lane == 0) {
        g_weights[gw] = sum;
        g_wt[(size_t)bb * 3 * NN + n]          = w0;
        g_wt[(size_t)bb * 3 * NN + NN + n]     = w1;
        g_wt[(size_t)bb * 3 * NN + 2 * NN + n] = w2;
    }
}

// ---------------- per-batch Procrustes (double accumulation, fp32 3x3 SVD) ----------------
__device__ double block_reduce_d(double v, double* sred, int tid) {
    sred[tid] = v; __syncthreads();
    for (int s = 128; s > 0; s >>= 1) {
        if (tid < s) sred[tid] += sred[tid + s];
        __syncthreads();
    }
    double r = sred[0]; __syncthreads();
    return r;
}

__global__ __launch_bounds__(256) void procrustes_kernel(const float* __restrict__ src,
                                                         float* __restrict__ out) {
    const int bb = blockIdx.x, tid = threadIdx.x;
    __shared__ double sred[256];
    __shared__ double bc[16];

    const float* w  = g_weights + bb * NN;
    const float* wt = g_wt + (size_t)bb * 3 * NN;
    const float* sp = src + (size_t)bb * 3 * NN;

    double lv = 0.0;
    for (int n = tid; n < NN; n += 256) lv += (double)w[n];
    double wsum = block_reduce_d(lv, sred, tid);
    double denom = wsum + 1e-8;

    double acc[6] = {0, 0, 0, 0, 0, 0};
    for (int n = tid; n < NN; n += 256) {
        double wn = (double)w[n] / denom;
        acc[0] += (double)sp[n] * wn;
        acc[1] += (double)sp[NN + n] * wn;
        acc[2] += (double)sp[2 * NN + n] * wn;
        acc[3] += (double)wt[n] * wn;
        acc[4] += (double)wt[NN + n] * wn;
        acc[5] += (double)wt[2 * NN + n] * wn;
    }
    for (int q = 0; q < 6; q++) {
        double r = block_reduce_d(acc[q], sred, tid);
        if (tid == 0) bc[q] = r;
    }
    __syncthreads();
    double scent[3] = {bc[0], bc[1], bc[2]};
    double tcent[3] = {bc[3], bc[4], bc[5]};

    double h[9] = {0, 0, 0, 0, 0, 0, 0, 0, 0};
    for (int n = tid; n < NN; n += 256) {
        double wn = (double)w[n] / denom;
        double si[3] = {(double)sp[n] - scent[0],
                        (double)sp[NN + n] - scent[1],
                        (double)sp[2 * NN + n] - scent[2]};
        double tj[3] = {((double)wt[n] - tcent[0]) * wn,
                        ((double)wt[NN + n] - tcent[1]) * wn,
                        ((double)wt[2 * NN + n] - tcent[2]) * wn};
#pragma unroll
        for (int i = 0; i < 3; i++)
#pragma unroll
            for (int j = 0; j < 3; j++) h[i * 3 + j] += si[i] * tj[j];
    }
    for (int q = 0; q < 9; q++) {
        double r = block_reduce_d(h[q], sred, tid);
        if (tid == 0) bc[q] = r;
    }
    __syncthreads();

    if (tid == 0) {
        float H[3][3];
        for (int i = 0; i < 3; i++)
            for (int j = 0; j < 3; j++) H[i][j] = (float)bc[i * 3 + j];

        // A = H^T H, fp32 Jacobi eigendecomposition (18 sweeps = 6 full cycles)
        float A[3][3];
        for (int i = 0; i < 3; i++)
            for (int j = 0; j < 3; j++)
                A[i][j] = H[0][i] * H[0][j] + H[1][i] * H[1][j] + H[2][i] * H[2][j];
        float V[3][3] = {{1, 0, 0}, {0, 1, 0}, {0, 0, 1}};
#pragma unroll 1
        for (int sweep = 0; sweep < 18; sweep++) {
            int r3 = sweep % 3;
            int p = (r3 == 2) ? 1 : 0;
            int q = (r3 == 0) ? 1 : 2;
            float apq = A[p][q];
            if (fabsf(apq) < 1e-30f) continue;
            float theta = (A[q][q] - A[p][p]) / (2.0f * apq);
            float tt = copysignf(1.0f, theta) / (fabsf(theta) + sqrtf(theta * theta + 1.0f));
            float cc = rsqrtf(tt * tt + 1.0f);
            float ssn = tt * cc;
            for (int k = 0; k < 3; k++) {
                float akp = A[k][p], akq = A[k][q];
                A[k][p] = cc * akp - ssn * akq;
                A[k][q] = ssn * akp + cc * akq;
            }
            for (int k = 0; k < 3; k++) {
                float apk = A[p][k], aqk = A[q][k];
                A[p][k] = cc * apk - ssn * aqk;
                A[q][k] = ssn * apk + cc * aqk;
            }
            for (int k = 0; k < 3; k++) {
                float vkp = V[k][p], vkq = V[k][q];
                V[k][p] = cc * vkp - ssn * vkq;
                V[k][q] = ssn * vkp + cc * vkq;
            }
        }
        float ev[3] = {A[0][0], A[1][1], A[2][2]};
        int idx[3] = {0, 1, 2};
        if (ev[idx[0]] < ev[idx[1]]) { int t2 = idx[0]; idx[0] = idx[1]; idx[1] = t2; }
        if (ev[idx[0]] < ev[idx[2]]) { int t2 = idx[0]; idx[0] = idx[2]; idx[2] = t2; }
        if (ev[idx[1]] < ev[idx[2]]) { int t2 = idx[1]; idx[1] = idx[2]; idx[2] = t2; }

        float Vs[3][3], U[3][3];
        for (int k = 0; k < 3; k++) {
            int c = idx[k];
            float sv = sqrtf(fmaxf(ev[c], 0.0f));
            float invs = (sv > 1e-20f) ? 1.0f / sv : 0.0f;
            for (int i = 0; i < 3; i++) Vs[i][k] = V[i][c];
            for (int i = 0; i < 3; i++)
                U[i][k] = (H[i][0] * V[0][c] + H[i][1] * V[1][c] + H[i][2] * V[2][c]) * invs;
        }
        float detH = H[0][0] * (H[1][1] * H[2][2] - H[1][2] * H[2][1])
                   - H[0][1] * (H[1][0] * H[2][2] - H[1][2] * H[2][0])
                   + H[0][2] * (H[1][0] * H[2][1] - H[1][1] * H[2][0]);
        float dsg = (detH >= 0.0f) ? 1.0f : -1.0f;
        float R[3][3];
        for (int i = 0; i < 3; i++)
            for (int j = 0; j < 3; j++)
                R[i][j] = Vs[i][0] * U[j][0] + Vs[i][1] * U[j][1] + dsg * Vs[i][2] * U[j][2];
        float tv[3];
        for (int i = 0; i < 3; i++)
            tv[i] = -(R[i][0] * (float)scent[0] + R[i][1] * (float)scent[1]
                      + R[i][2] * (float)scent[2]) + (float)tcent[i];

        for (int i = 0; i < 3; i++)
            for (int j = 0; j < 3; j++)
                out[bb * 9 + i * 3 + j] = R[i][j];
        for (int i = 0; i < 3; i++)
            out[BB * 9 + bb * 3 + i] = tv[i];
    }
}

// ---------------- launch ----------------
extern "C" void kernel_launch(void* const* d_in, const int* in_sizes, int n_in,
                              void* d_out, int out_size) {
    const float* src_emb = (const float*)d_in[0];
    const float* tgt_emb = (const float*)d_in[1];
    const float* src     = (const float*)d_in[2];
    const float* tgt     = (const float*)d_in[3];
    const float* temp    = (const float*)d_in[4];
    float* out = (float*)d_out;
    float* out_pn = out + BB * 9 + BB * 3;

    init_kernel<<<64, 256>>>();                                             // our 0
    convert_kernel<<<dim3(NN / 32, DKK / 32, 2 * BB), dim3(256)>>>(src_emb, tgt_emb); // 1

    const int gemm_smem = 3 * STG_B;   // 192 KB
    cudaFuncSetAttribute(gemm_mma, cudaFuncAttributeMaxDynamicSharedMemorySize, gemm_smem);
    gemm_mma<<<dim3(MMM / 128, NN / 128, BB), 512, gemm_smem>>>(temp);      // 2

    for (int it = 0; it < 5; it++) {
        row_kernel<<<(BB * NN) / 8, 256>>>();                               // 3 (it=0) -> profiled
        colreduce_kernel<<<(BB * MMM) / 256, 256>>>();
    }
    final_kernel<<<(BB * NN) / 8, 256>>>(tgt, out_pn);
    procrustes_kernel<<<BB, 256>>>(src, out);
}

// round 9
// speedup vs baseline: 2.5858x; 1.0352x over previous
#include <cuda_runtime.h>
#include <cuda_bf16.h>
#include <math.h>
#include <stdint.h>

#define BB 16
#define DKK 512
#define NN 1024
#define MMM 1024

// ---------------- scratch (device globals) ----------------
__device__ float g_scores[(size_t)BB * NN * MMM];
__device__ __nv_bfloat16 g_shi[(size_t)BB * NN * DKK];
__device__ __nv_bfloat16 g_slo[(size_t)BB * NN * DKK];
__device__ __nv_bfloat16 g_thi[(size_t)BB * MMM * DKK];
__device__ __nv_bfloat16 g_tlo[(size_t)BB * MMM * DKK];
__device__ float g_cp[(size_t)BB * 128 * MMM];
__device__ float g_r[BB * NN];
__device__ float g_c[BB * MMM];
__device__ float g_weights[BB * NN];
__device__ float g_wt[BB * 3 * NN];

// ---------------- PTX helpers ----------------
__device__ __forceinline__ uint32_t smem_u32(const void* p) {
    uint32_t a;
    asm("{ .reg .u64 t; cvta.to.shared.u64 t, %1; cvt.u32.u64 %0, t; }" : "=r"(a) : "l"(p));
    return a;
}
#define LDSM4(r0, r1, r2, r3, addr) \
    asm volatile("ldmatrix.sync.aligned.m8n8.x4.shared.b16 {%0,%1,%2,%3}, [%4];" \
        : "=r"(r0), "=r"(r1), "=r"(r2), "=r"(r3) : "r"(addr))
#define MMA16816(c, a, b0, b1) \
    asm volatile("mma.sync.aligned.m16n8k16.row.col.f32.bf16.bf16.f32 " \
        "{%0,%1,%2,%3}, {%4,%5,%6,%7}, {%8,%9}, {%0,%1,%2,%3};" \
        : "+f"((c)[0]), "+f"((c)[1]), "+f"((c)[2]), "+f"((c)[3]) \
        : "r"((a)[0]), "r"((a)[1]), "r"((a)[2]), "r"((a)[3]), "r"(b0), "r"(b1))
#define CPASYNC16(saddr, gptr) \
    asm volatile("cp.async.cg.shared.global [%0], [%1], 16;" :: "r"(saddr), "l"(gptr))
#define CP_COMMIT() asm volatile("cp.async.commit_group;" ::: "memory")
#define CP_WAIT1()  asm volatile("cp.async.wait_group 1;" ::: "memory")
#define CP_WAIT0()  asm volatile("cp.async.wait_group 0;" ::: "memory")

__device__ __forceinline__ uint32_t sw128(uint32_t off) {
    return off ^ ((off >> 3) & 0x70);
}
__device__ __forceinline__ void stg_evl8(float* p, float4 v0, float4 v1) {
    asm volatile("st.global.L2::evict_last.v8.b32 [%0], {%1,%2,%3,%4,%5,%6,%7,%8};"
                 :: "l"(p),
                    "r"(__float_as_uint(v0.x)), "r"(__float_as_uint(v0.y)),
                    "r"(__float_as_uint(v0.z)), "r"(__float_as_uint(v0.w)),
                    "r"(__float_as_uint(v1.x)), "r"(__float_as_uint(v1.y)),
                    "r"(__float_as_uint(v1.z)), "r"(__float_as_uint(v1.w)) : "memory");
}

// ---------------- init: zero column duals ----------------
__global__ void init_kernel() {
    int i = blockIdx.x * blockDim.x + threadIdx.x;
    if (i < BB * MMM) g_c[i] = 0.0f;
}

// spacer so profiled slot (our launch #3) = gemm_mma
__global__ void dummy_kernel() {
    if (threadIdx.x == 0) g_cp[0] = 0.0f;
}

// ---------------- transpose + hi/lo bf16 split ----------------
__global__ __launch_bounds__(256) void convert_kernel(const float* __restrict__ srcE,
                                                      const float* __restrict__ tgtE) {
    __shared__ float s[32][33];
    const int z = blockIdx.z;
    const int bb = z & 15;
    const float* in = (z < 16) ? srcE : tgtE;
    __nv_bfloat16* hi = (z < 16) ? g_shi : g_thi;
    __nv_bfloat16* lo = (z < 16) ? g_slo : g_tlo;
    const int tid = threadIdx.x;
    const int tx = tid & 31, ty = tid >> 5;
    const int n = blockIdx.x * 32 + tx;
    const int d0 = blockIdx.y * 32;
#pragma unroll
    for (int j = 0; j < 4; j++)
        s[ty + 8 * j][tx] = in[((size_t)bb * DKK + d0 + ty + 8 * j) * NN + n];
    __syncthreads();
#pragma unroll
    for (int q = 0; q < 2; q++) {
        int p = tid + q * 256;
        int nl = p >> 4;
        int d = (p & 15) * 2;
        int nn = blockIdx.x * 32 + nl;
        float v0 = s[d][nl], v1 = s[d + 1][nl];
        __nv_bfloat16 h0 = __float2bfloat16(v0), h1 = __float2bfloat16(v1);
        float r0 = v0 - __bfloat162float(h0), r1 = v1 - __bfloat162float(h1);
        size_t o = ((size_t)bb * NN + nn) * DKK + d0 + d;
        *(__nv_bfloat162*)(hi + o) = __nv_bfloat162(h0, h1);
        *(__nv_bfloat162*)(lo + o) = __nv_bfloat162(__float2bfloat16(r0), __float2bfloat16(r1));
    }
}

// ---------------- bf16-split GEMM: 64x128 CTA tile, 256 thr, 2 CTAs/SM ----------------
// stage: Ah 64x128B (8K) @0, Al @8K, Bh 128x128B (16K) @16K, Bl @32K -> 48KB/stage, 2 stages.
#define STG2_B 49152

__global__ __launch_bounds__(256, 2) void gemm_mma(const float* __restrict__ temp) {
    extern __shared__ char sm_[];
    const uint32_t sb = smem_u32(sm_);
    const int tid = threadIdx.x, wid = tid >> 5, lane = tid & 31;
    const int mt = blockIdx.x, nt = blockIdx.y, bb = blockIdx.z;
    const int warp_m = wid & 1;     // 2 warps over 64 rows (32 each)
    const int warp_n = wid >> 1;    // 4 warps over 128 cols (32 each)

    const __nv_bfloat16* Ah = g_shi + ((size_t)bb * NN + nt * 64) * DKK;
    const __nv_bfloat16* Al = g_slo + ((size_t)bb * NN + nt * 64) * DKK;
    const __nv_bfloat16* Bh = g_thi + ((size_t)bb * MMM + mt * 128) * DKK;
    const __nv_bfloat16* Bl = g_tlo + ((size_t)bb * MMM + mt * 128) * DKK;

    // 3072 16B chunks per stage, 12 per thread; region boundaries align with i*256
    auto stage_load = [&](int kc, int s) {
#pragma unroll
        for (int i = 0; i < 12; i++) {
            int q = tid + i * 256;
            const __nv_bfloat16* base;
            uint32_t moff;
            int row;
            if (q < 512)       { base = Ah; moff = 0;     row = q >> 3; }
            else if (q < 1024) { base = Al; moff = 8192;  row = (q - 512) >> 3; }
            else if (q < 2048) { base = Bh; moff = 16384; row = (q - 1024) >> 3; }
            else               { base = Bl; moff = 32768; row = (q - 2048) >> 3; }
            int c = q & 7;
            uint32_t saddr = sb + (uint32_t)s * STG2_B + moff + sw128(row * 128 + c * 16);
            const char* g = (const char*)(base + (size_t)row * DKK + kc * 64 + c * 8);
            CPASYNC16(saddr, g);
        }
        CP_COMMIT();
    };

    float acc[2][4][4];
#pragma unroll
    for (int i = 0; i < 2; i++)
#pragma unroll
        for (int j = 0; j < 4; j++)
#pragma unroll
            for (int k = 0; k < 4; k++) acc[i][j][k] = 0.0f;

    stage_load(0, 0);
    stage_load(1, 1);

    for (int kc = 0; kc < 8; kc++) {
        const int s = kc & 1;
        if (kc + 1 < 8) { CP_WAIT1(); }
        else            { CP_WAIT0(); }
        __syncthreads();

        const uint32_t stg = sb + (uint32_t)s * STG2_B;

#pragma unroll
        for (int h = 0; h < 4; h++) {
            uint32_t ah[2][4], al[2][4], bh[2][4], bl[2][4];
#pragma unroll
            for (int mf = 0; mf < 2; mf++) {
                uint32_t off = (uint32_t)((warp_m * 32 + mf * 16 + (lane & 15)) * 128
                              + h * 32 + (lane >> 4) * 16);
                uint32_t ad = stg + sw128(off);
                LDSM4(ah[mf][0], ah[mf][1], ah[mf][2], ah[mf][3], ad);
                LDSM4(al[mf][0], al[mf][1], al[mf][2], al[mf][3], ad + 8192);
            }
#pragma unroll
            for (int np = 0; np < 2; np++) {
                uint32_t off = (uint32_t)((warp_n * 32 + np * 16 + ((lane >> 4) & 1) * 8 + (lane & 7)) * 128
                              + h * 32 + ((lane >> 3) & 1) * 16);
                uint32_t bd = stg + 16384 + sw128(off);
                LDSM4(bh[np][0], bh[np][1], bh[np][2], bh[np][3], bd);
                LDSM4(bl[np][0], bl[np][1], bl[np][2], bl[np][3], bd + 16384);
            }
#pragma unroll
            for (int mf = 0; mf < 2; mf++)
#pragma unroll
                for (int n8 = 0; n8 < 4; n8++) {
                    const int np = n8 >> 1, hf = (n8 & 1) * 2;
                    MMA16816(acc[mf][n8], ah[mf], bh[np][hf], bh[np][hf + 1]);
                }
#pragma unroll
            for (int mf = 0; mf < 2; mf++)
#pragma unroll
                for (int n8 = 0; n8 < 4; n8++) {
                    const int np = n8 >> 1, hf = (n8 & 1) * 2;
                    MMA16816(acc[mf][n8], ah[mf], bl[np][hf], bl[np][hf + 1]);
                }
#pragma unroll
            for (int mf = 0; mf < 2; mf++)
#pragma unroll
                for (int n8 = 0; n8 < 4; n8++) {
                    const int np = n8 >> 1, hf = (n8 & 1) * 2;
                    MMA16816(acc[mf][n8], al[mf], bh[np][hf], bh[np][hf + 1]);
                }
        }
        __syncthreads();                     // stage s free before reload at kc+2
        if (kc + 2 < 8) stage_load(kc + 2, s);
    }

    // ---- epilogue: stage through smem (132-float padded rows), 32B coalesced stores ----
    float* smF = (float*)sm_;
#pragma unroll
    for (int mf = 0; mf < 2; mf++)
#pragma unroll
        for (int n8 = 0; n8 < 4; n8++) {
            int r0 = warp_m * 32 + mf * 16 + (lane >> 2);
            int col = warp_n * 32 + n8 * 8 + (lane & 3) * 2;
            *(float2*)(smF + r0 * 132 + col)       = make_float2(acc[mf][n8][0], acc[mf][n8][1]);
            *(float2*)(smF + (r0 + 8) * 132 + col) = make_float2(acc[mf][n8][2], acc[mf][n8][3]);
        }
    __syncthreads();

    const float alpha = rsqrtf((float)DKK) / temp[bb];
    float* C = g_scores + (size_t)bb * NN * MMM + (size_t)(nt * 64) * MMM + mt * 128;
#pragma unroll
    for (int i = 0; i < 4; i++) {
        int idx = tid + i * 256;            // 0..1023 chunks of 8 floats
        int row = idx >> 4, c8 = idx & 15;
        const float* sp = smF + row * 132 + c8 * 8;
        float4 v0 = *(const float4*)sp;
        float4 v1 = *(const float4*)(sp + 4);
        v0.x *= alpha; v0.y *= alpha; v0.z *= alpha; v0.w *= alpha;
        v1.x *= alpha; v1.y *= alpha; v1.z *= alpha; v1.w *= alpha;
        stg_evl8(C + (size_t)row * MMM + c8 * 8, v0, v1);
    }
}

// ---------------- row pass ----------------
__global__ __launch_bounds__(256) void row_kernel() {
    __shared__ float s_aff[8][1024];
    __shared__ float s_c[1024];
    const int tid  = threadIdx.x;
    const int w    = tid >> 5;
    const int lane = tid & 31;
    const int gw   = blockIdx.x * 8 + w;
    const int bb   = gw >> 10;
    const uint32_t sb_aff = smem_u32(&s_aff[0][0]);
    const uint32_t sb_c   = smem_u32(&s_c[0]);

    CPASYNC16(sb_c + tid * 16, (const char*)(g_c + bb * MMM + tid * 4));
    const float* affbase = g_scores + (size_t)(blockIdx.x * 8) * MMM;
#pragma unroll
    for (int i = 0; i < 8; i++) {
        int q = tid + i * 256;
        CPASYNC16(sb_aff + q * 16, (const char*)(affbase + (size_t)(q >> 8) * MMM + (q & 255) * 4));
    }
    CP_COMMIT();
    CP_WAIT0();
    __syncthreads();

    float x[32];
    float mx = 0.0f;
#pragma unroll
    for (int i = 0; i < 8; i++) {
        int off = i * 128 + lane * 4;
        float4 a = *(const float4*)(&s_aff[w][off]);
        float4 cc = *(const float4*)(&s_c[off]);
        x[4 * i]     = a.x - cc.x;
        x[4 * i + 1] = a.y - cc.y;
        x[4 * i + 2] = a.z - cc.z;
        x[4 * i + 3] = a.w - cc.w;
        mx = fmaxf(mx, fmaxf(fmaxf(x[4 * i], x[4 * i + 1]), fmaxf(x[4 * i + 2], x[4 * i + 3])));
    }
#pragma unroll
    for (int o = 16; o > 0; o >>= 1) mx = fmaxf(mx, __shfl_xor_sync(0xffffffffu, mx, o));

    float s = 0.0f;
#pragma unroll
    for (int i = 0; i < 32; i++) { x[i] = __expf(x[i] - mx); s += x[i]; }
#pragma unroll
    for (int o = 16; o > 0; o >>= 1) s += __shfl_xor_sync(0xffffffffu, s, o);
    s += __expf(-mx);

    const float r = mx + logf(s);
    if (lane == 0) g_r[gw] = r;
    const float scale = __expf(mx - r);

    __syncthreads();
#pragma unroll
    for (int i = 0; i < 8; i++) {
        int off = i * 128 + lane * 4;
        float4 e;
        e.x = x[4 * i] * scale;     e.y = x[4 * i + 1] * scale;
        e.z = x[4 * i + 2] * scale; e.w = x[4 * i + 3] * scale;
        *(float4*)(&s_aff[w][off]) = e;
    }
    __syncthreads();

    float4 acc = *(const float4*)(&s_aff[0][tid * 4]);
#pragma unroll
    for (int ww = 1; ww < 8; ww++) {
        float4 v = *(const float4*)(&s_aff[ww][tid * 4]);
        acc.x += v.x; acc.y += v.y; acc.z += v.z; acc.w += v.w;
    }
    const int rb = blockIdx.x & 127;
    *(float4*)(g_cp + ((size_t)(bb * 128 + rb)) * 1024 + tid * 4) = acc;
}

// ---------------- column reduce ----------------
__global__ __launch_bounds__(256) void colreduce_kernel() {
    const int idx = blockIdx.x * 256 + threadIdx.x;
    const int b = idx >> 10, m = idx & 1023;
    const float* cp = g_cp + (size_t)b * 128 * 1024 + m;
    float S = 0.0f;
#pragma unroll 8
    for (int rb = 0; rb < 128; rb++) S += cp[(size_t)rb * 1024];
    const float co = g_c[idx];
    g_c[idx] = co + logf(S + __expf(-co));
}

// ---------------- final: perm_norm, weights, weighted_tgt ----------------
__global__ __launch_bounds__(256) void final_kernel(const float* __restrict__ tgt,
                                                    float* __restrict__ out_pn) {
    const int gw   = (blockIdx.x * 256 + threadIdx.x) >> 5;
    const int lane = threadIdx.x & 31;
    const int bb   = gw >> 10;
    const int n    = gw & 1023;
    const float* aff = g_scores + (size_t)gw * MMM;
    const float* c   = g_c + bb * MMM;
    const float r    = g_r[gw];

    float p[32];
    float sum = 0.0f;
#pragma unroll
    for (int i = 0; i < 8; i++) {
        int off = i * 128 + lane * 4;
        float4 a = *(const float4*)(aff + off);
        float4 cc = *(const float4*)(c + off);
        float p0 = __expf(a.x - cc.x - r), p1 = __expf(a.y - cc.y - r);
        float p2 = __expf(a.z - cc.z - r), p3 = __expf(a.w - cc.w - r);
        p[4 * i] = p0; p[4 * i + 1] = p1; p[4 * i + 2] = p2; p[4 * i + 3] = p3;
        sum += p0 + p1 + p2 + p3;
    }
#pragma unroll
    for (int o = 16; o > 0; o >>= 1) sum += __shfl_xor_sync(0xffffffffu, sum, o);

    const float inv = 1.0f / (sum + 1e-8f);
    const float* t0 = tgt + (size_t)bb * 3 * MMM;
    float w0 = 0.0f, w1 = 0.0f, w2 = 0.0f;
    float* outrow = out_pn + (size_t)gw * MMM;
#pragma unroll
    for (int i = 0; i < 8; i++) {
        int off = i * 128 + lane * 4;
        float4 q;
        q.x = p[4 * i] * inv; q.y = p[4 * i + 1] * inv;
        q.z = p[4 * i + 2] * inv; q.w = p[4 * i + 3] * inv;
        __stcs((float4*)(outrow + off), q);
        float4 ta = *(const float4*)(t0 + off);
        float4 tb = *(const float4*)(t0 + MMM + off);
        float4 tc = *(const float4*)(t0 + 2 * MMM + off);
        w0 += q.x * ta.x + q.y * ta.y + q.z * ta.z + q.w * ta.w;
        w1 += q.x * tb.x + q.y * tb.y + q.z * tb.z + q.w * tb.w;
        w2 += q.x * tc.x + q.y * tc.y + q.z * tc.z + q.w * tc.w;
    }
#pragma unroll
    for (int o = 16; o > 0; o >>= 1) {
        w0 += __shfl_xor_sync(0xffffffffu, w0, o);
        w1 += __shfl_xor_sync(0xffffffffu, w1, o);
        w2 += __shfl_xor_sync(0xffffffffu, w2, o);
    }
    if (lane == 0) {
        g_weights[gw] = sum;
        g_wt[(size_t)bb * 3 * NN + n]          = w0;
        g_wt[(size_t)bb * 3 * NN + NN + n]     = w1;
        g_wt[(size_t)bb * 3 * NN + 2 * NN + n] = w2;
    }
}

// ---------------- per-batch Procrustes (double accumulation, fp32 3x3 SVD) ----------------
__device__ double block_reduce_d(double v, double* sred, int tid) {
    sred[tid] = v; __syncthreads();
    for (int s = 128; s > 0; s >>= 1) {
        if (tid < s) sred[tid] += sred[tid + s];
        __syncthreads();
    }
    double r = sred[0]; __syncthreads();
    return r;
}

__global__ __launch_bounds__(256) void procrustes_kernel(const float* __restrict__ src,
                                                         float* __restrict__ out) {
    const int bb = blockIdx.x, tid = threadIdx.x;
    __shared__ double sred[256];
    __shared__ double bc[16];

    const float* w  = g_weights + bb * NN;
    const float* wt = g_wt + (size_t)bb * 3 * NN;
    const float* sp = src + (size_t)bb * 3 * NN;

    double lv = 0.0;
    for (int n = tid; n < NN; n += 256) lv += (double)w[n];
    double wsum = block_reduce_d(lv, sred, tid);
    double denom = wsum + 1e-8;

    double acc[6] = {0, 0, 0, 0, 0, 0};
    for (int n = tid; n < NN; n += 256) {
        double wn = (double)w[n] / denom;
        acc[0] += (double)sp[n] * wn;
        acc[1] += (double)sp[NN + n] * wn;
        acc[2] += (double)sp[2 * NN + n] * wn;
        acc[3] += (double)wt[n] * wn;
        acc[4] += (double)wt[NN + n] * wn;
        acc[5] += (double)wt[2 * NN + n] * wn;
    }
    for (int q = 0; q < 6; q++) {
        double r = block_reduce_d(acc[q], sred, tid);
        if (tid == 0) bc[q] = r;
    }
    __syncthreads();
    double scent[3] = {bc[0], bc[1], bc[2]};
    double tcent[3] = {bc[3], bc[4], bc[5]};

    double h[9] = {0, 0, 0, 0, 0, 0, 0, 0, 0};
    for (int n = tid; n < NN; n += 256) {
        double wn = (double)w[n] / denom;
        double si[3] = {(double)sp[n] - scent[0],
                        (double)sp[NN + n] - scent[1],
                        (double)sp[2 * NN + n] - scent[2]};
        double tj[3] = {((double)wt[n] - tcent[0]) * wn,
                        ((double)wt[NN + n] - tcent[1]) * wn,
                        ((double)wt[2 * NN + n] - tcent[2]) * wn};
#pragma unroll
        for (int i = 0; i < 3; i++)
#pragma unroll
            for (int j = 0; j < 3; j++) h[i * 3 + j] += si[i] * tj[j];
    }
    for (int q = 0; q < 9; q++) {
        double r = block_reduce_d(h[q], sred, tid);
        if (tid == 0) bc[q] = r;
    }
    __syncthreads();

    if (tid == 0) {
        float H[3][3];
        for (int i = 0; i < 3; i++)
            for (int j = 0; j < 3; j++) H[i][j] = (float)bc[i * 3 + j];

        float A[3][3];
        for (int i = 0; i < 3; i++)
            for (int j = 0; j < 3; j++)
                A[i][j] = H[0][i] * H[0][j] + H[1][i] * H[1][j] + H[2][i] * H[2][j];
        float V[3][3] = {{1, 0, 0}, {0, 1, 0}, {0, 0, 1}};
#pragma unroll 1
        for (int sweep = 0; sweep < 18; sweep++) {
            int r3 = sweep % 3;
            int p = (r3 == 2) ? 1 : 0;
            int q = (r3 == 0) ? 1 : 2;
            float apq = A[p][q];
            if (fabsf(apq) < 1e-30f) continue;
            float theta = (A[q][q] - A[p][p]) / (2.0f * apq);
            float tt = copysignf(1.0f, theta) / (fabsf(theta) + sqrtf(theta * theta + 1.0f));
            float cc = rsqrtf(tt * tt + 1.0f);
            float ssn = tt * cc;
            for (int k = 0; k < 3; k++) {
                float akp = A[k][p], akq = A[k][q];
                A[k][p] = cc * akp - ssn * akq;
                A[k][q] = ssn * akp + cc * akq;
            }
            for (int k = 0; k < 3; k++) {
                float apk = A[p][k], aqk = A[q][k];
                A[p][k] = cc * apk - ssn * aqk;
                A[q][k] = ssn * apk + cc * aqk;
            }
            for (int k = 0; k < 3; k++) {
                float vkp = V[k][p], vkq = V[k][q];
                V[k][p] = cc * vkp - ssn * vkq;
                V[k][q] = ssn * vkp + cc * vkq;
            }
        }
        float ev[3] = {A[0][0], A[1][1], A[2][2]};
        int idx[3] = {0, 1, 2};
        if (ev[idx[0]] < ev[idx[1]]) { int t2 = idx[0]; idx[0] = idx[1]; idx[1] = t2; }
        if (ev[idx[0]] < ev[idx[2]]) { int t2 = idx[0]; idx[0] = idx[2]; idx[2] = t2; }
        if (ev[idx[1]] < ev[idx[2]]) { int t2 = idx[1]; idx[1] = idx[2]; idx[2] = t2; }

        float Vs[3][3], U[3][3];
        for (int k = 0; k < 3; k++) {
            int c = idx[k];
            float sv = sqrtf(fmaxf(ev[c], 0.0f));
            float invs = (sv > 1e-20f) ? 1.0f / sv : 0.0f;
            for (int i = 0; i < 3; i++) Vs[i][k] = V[i][c];
            for (int i = 0; i < 3; i++)
                U[i][k] = (H[i][0] * V[0][c] + H[i][1] * V[1][c] + H[i][2] * V[2][c]) * invs;
        }
        float detH = H[0][0] * (H[1][1] * H[2][2] - H[1][2] * H[2][1])
                   - H[0][1] * (H[1][0] * H[2][2] - H[1][2] * H[2][0])
                   + H[0][2] * (H[1][0] * H[2][1] - H[1][1] * H[2][0]);
        float dsg = (detH >= 0.0f) ? 1.0f : -1.0f;
        float R[3][3];
        for (int i = 0; i < 3; i++)
            for (int j = 0; j < 3; j++)
                R[i][j] = Vs[i][0] * U[j][0] + Vs[i][1] * U[j][1] + dsg * Vs[i][2] * U[j][2];
        float tv[3];
        for (int i = 0; i < 3; i++)
            tv[i] = -(R[i][0] * (float)scent[0] + R[i][1] * (float)scent[1]
                      + R[i][2] * (float)scent[2]) + (float)tcent[i];

        for (int i = 0; i < 3; i++)
            for (int j = 0; j < 3; j++)
                out[bb * 9 + i * 3 + j] = R[i][j];
        for (int i = 0; i < 3; i++)
            out[BB * 9 + bb * 3 + i] = tv[i];
    }
}

// ---------------- launch ----------------
extern "C" void kernel_launch(void* const* d_in, const int* in_sizes, int n_in,
                              void* d_out, int out_size) {
    const float* src_emb = (const float*)d_in[0];
    const float* tgt_emb = (const float*)d_in[1];
    const float* src     = (const float*)d_in[2];
    const float* tgt     = (const float*)d_in[3];
    const float* temp    = (const float*)d_in[4];
    float* out = (float*)d_out;
    float* out_pn = out + BB * 9 + BB * 3;

    init_kernel<<<64, 256>>>();                                             // our 0
    convert_kernel<<<dim3(NN / 32, DKK / 32, 2 * BB), dim3(256)>>>(src_emb, tgt_emb); // 1
    dummy_kernel<<<1, 32>>>();                                              // 2

    const int gemm_smem = 2 * STG2_B;   // 96 KB per CTA; 2 CTAs/SM
    cudaFuncSetAttribute(gemm_mma, cudaFuncAttributeMaxDynamicSharedMemorySize, gemm_smem);
    gemm_mma<<<dim3(MMM / 128, NN / 64, BB), 256, gemm_smem>>>(temp);       // 3 -> profiled

    for (int it = 0; it < 5; it++) {
        row_kernel<<<(BB * NN) / 8, 256>>>();
        colreduce_kernel<<<(BB * MMM) / 256, 256>>>();
    }
    final_kernel<<<(BB * NN) / 8, 256>>>(tgt, out_pn);
    procrustes_kernel<<<BB, 256>>>(src, out);
}